// round 6
// baseline (speedup 1.0000x reference)
#include <cuda_runtime.h>
#include <math.h>

#define Nn 8192
#define IN_F 256
#define OUT_F 128
#define NWORDS 256   // bitmap words per row (8192 bits)
#define CAP 2048     // fast-path neighbor list capacity (expected degree ~32)

// ---------------- device scratch (no allocs allowed) ----------------
__device__ float    g_hc[Nn * OUT_F];          // 4 MB
__device__ unsigned g_adj[Nn * NWORDS];        // 8 MB adjacency bitmap
__device__ float    g_sc_src[Nn];
__device__ float    g_ss_src[Nn];
__device__ float2   g_sd[Nn];                  // (sc_dst, ss_dst) packed
__device__ float    g_vs1[IN_F], g_vs2[IN_F];  // hs-GEMM fold vectors
__device__ float    g_scal[4];                 // ca, cs, bs1, bs2
__device__ int      g_isi32 = 0;               // reset at end of k_attn

__device__ __forceinline__ float lrelu(float x) { return x > 0.f ? x : 0.01f * x; }

// ---------------- reductions (start and end with __syncthreads) ----------------
__device__ float blockReduceMax(float v, float* red) {
    __syncthreads();
    #pragma unroll
    for (int o = 16; o; o >>= 1) v = fmaxf(v, __shfl_xor_sync(0xffffffffu, v, o));
    int w = threadIdx.x >> 5;
    if ((threadIdx.x & 31) == 0) red[w] = v;
    __syncthreads();
    if (threadIdx.x < 32) {
        float x = (threadIdx.x < (blockDim.x >> 5)) ? red[threadIdx.x] : -INFINITY;
        #pragma unroll
        for (int o = 4; o; o >>= 1) x = fmaxf(x, __shfl_xor_sync(0xffffffffu, x, o));
        if (threadIdx.x == 0) red[0] = x;
    }
    __syncthreads();
    return red[0];
}

__device__ float blockReduceSum(float v, float* red) {
    __syncthreads();
    #pragma unroll
    for (int o = 16; o; o >>= 1) v += __shfl_xor_sync(0xffffffffu, v, o);
    int w = threadIdx.x >> 5;
    if ((threadIdx.x & 31) == 0) red[w] = v;
    __syncthreads();
    if (threadIdx.x < 32) {
        float x = (threadIdx.x < (blockDim.x >> 5)) ? red[threadIdx.x] : 0.f;
        #pragma unroll
        for (int o = 4; o; o >>= 1) x += __shfl_xor_sync(0xffffffffu, x, o);
        if (threadIdx.x == 0) red[0] = x;
    }
    __syncthreads();
    return red[0];
}

// ---------------- kernels ----------------
// Fused: vectorized bitmap clear + int32/int64 detection + g_vs zero (block 0).
__global__ void k_init(const int* __restrict__ p32, int E) {
    int i = blockIdx.x * blockDim.x + threadIdx.x;
    ((uint4*)g_adj)[i] = make_uint4(0u, 0u, 0u, 0u);
    if (blockIdx.x == 0) {
        g_vs1[threadIdx.x] = 0.f;
        g_vs2[threadIdx.x] = 0.f;
    }
    if (i < E) {
        if (p32[2 * i + 1] != 0) atomicOr(&g_isi32, 1);
    }
}

// Edge bitmap build; blocks 0..7 also accumulate the hs-GEMM fold
// (vs = Ws_w^T @ as_half) via coalesced partials + atomicAdd; block 8 does
// bias dots + coefficient abs.
__global__ void k_edges(const int* __restrict__ p32, int E,
                        const float* __restrict__ Ws_w,
                        const float* __restrict__ Ws_b,
                        const float* __restrict__ as_w,
                        const float* __restrict__ Ws_coff,
                        const float* __restrict__ Wc_coff) {
    int tid = threadIdx.x;
    int e = blockIdx.x * blockDim.x + tid;
    if (e < E) {
        int r, c;
        if (g_isi32) {
            r = p32[e];
            c = p32[E + e];
        } else {
            const long long* p64 = (const long long*)p32;
            r = (int)p64[e];
            c = (int)p64[E + e];
        }
        if ((unsigned)r < Nn && (unsigned)c < Nn)
            atomicOr(&g_adj[r * NWORDS + (c >> 5)], 1u << (c & 31));
    }
    if (blockIdx.x < 8) {
        float v1 = 0.f, v2 = 0.f;
        #pragma unroll
        for (int i = 0; i < 16; i++) {
            int f = blockIdx.x * 16 + i;
            float w = Ws_w[f * IN_F + tid];
            v1 += w * as_w[f];
            v2 += w * as_w[OUT_F + f];
        }
        atomicAdd(&g_vs1[tid], v1);
        atomicAdd(&g_vs2[tid], v2);
    } else if (blockIdx.x == 8 && tid < 32) {
        float b1 = 0.f, b2 = 0.f;
        #pragma unroll
        for (int i = 0; i < 4; i++) {
            int f = tid + 32 * i;
            float wb = Ws_b[f];
            b1 += wb * as_w[f];
            b2 += wb * as_w[OUT_F + f];
        }
        #pragma unroll
        for (int o = 16; o; o >>= 1) {
            b1 += __shfl_xor_sync(0xffffffffu, b1, o);
            b2 += __shfl_xor_sync(0xffffffffu, b2, o);
        }
        if (tid == 0) {
            g_scal[0] = fabsf(Ws_coff[0]);  // multiplies alpha_c
            g_scal[1] = fabsf(Wc_coff[0]);  // multiplies alpha_s
            g_scal[2] = b1;
            g_scal[3] = b2;
        }
    }
}

// Structure scores: warp per row, softmax over 256 features dotted with g_vs.
__global__ void k_sscore(const float* __restrict__ hstruct) {
    int warp = (blockIdx.x * blockDim.x + threadIdx.x) >> 5;
    int lane = threadIdx.x & 31;
    if (warp >= Nn) return;
    const float* x = hstruct + (size_t)warp * IN_F;
    float v[8], w1[8], w2[8];
    float m = -INFINITY;
    #pragma unroll
    for (int e = 0; e < 8; e++) {
        v[e]  = x[lane + 32 * e];
        w1[e] = g_vs1[lane + 32 * e];
        w2[e] = g_vs2[lane + 32 * e];
        m = fmaxf(m, v[e]);
    }
    #pragma unroll
    for (int o = 16; o; o >>= 1) m = fmaxf(m, __shfl_xor_sync(0xffffffffu, m, o));
    float z = 0.f, d1 = 0.f, d2 = 0.f;
    #pragma unroll
    for (int e = 0; e < 8; e++) {
        float ex = __expf(v[e] - m);
        z  += ex;
        d1 += ex * w1[e];
        d2 += ex * w2[e];
    }
    #pragma unroll
    for (int o = 16; o; o >>= 1) {
        z  += __shfl_xor_sync(0xffffffffu, z,  o);
        d1 += __shfl_xor_sync(0xffffffffu, d1, o);
        d2 += __shfl_xor_sync(0xffffffffu, d2, o);
    }
    if (lane == 0) {
        g_ss_src[warp] = d1 / z + g_scal[2];
        g_sd[warp].y   = d2 / z + g_scal[3];
    }
}

// hc = h_context @ Wc_w^T + Wc_b  (M=8192, N=128, K=256) fp32 SGEMM.
// BM=32 -> grid 256 blocks -> all 148 SMs busy, 1-2 blocks/SM.
#define BM 32
#define BN 128
#define BK 32
#define KTILES (IN_F / BK)
__global__ void __launch_bounds__(256) k_gemm(const float* __restrict__ A,
                                              const float* __restrict__ W,
                                              const float* __restrict__ b,
                                              const float* __restrict__ ac_w) {
    __shared__ float As[2][BK][BM + 4];
    __shared__ float Ws[2][BK][BN + 4];
    int tid = threadIdx.x;
    int lane = tid & 31;
    int warp = tid >> 5;
    int block_m = blockIdx.x * BM;
    int tn = lane * 4;     // 0..124
    int tm = warp * 4;     // 0..28

    int r0 = tid >> 3;             // 0..31
    int c0 = (tid & 7) * 4;        // 0..28
    const float* Aptr = &A[(size_t)(block_m + r0) * IN_F + c0];
    const float* Wptr = &W[(size_t)r0 * IN_F + c0];

    float4 ra, rw0, rw1, rw2, rw3;
    #define LDG_TILE(k0)                                                    \
        ra  = *(const float4*)(Aptr + (k0));                                \
        rw0 = *(const float4*)(Wptr + (k0));                                \
        rw1 = *(const float4*)(Wptr + (size_t)32 * IN_F + (k0));            \
        rw2 = *(const float4*)(Wptr + (size_t)64 * IN_F + (k0));            \
        rw3 = *(const float4*)(Wptr + (size_t)96 * IN_F + (k0));

    #define STS_TILE(buf)                                                   \
        {                                                                   \
            As[buf][c0 + 0][r0] = ra.x;  As[buf][c0 + 1][r0] = ra.y;        \
            As[buf][c0 + 2][r0] = ra.z;  As[buf][c0 + 3][r0] = ra.w;        \
            Ws[buf][c0 + 0][r0] = rw0.x; Ws[buf][c0 + 1][r0] = rw0.y;       \
            Ws[buf][c0 + 2][r0] = rw0.z; Ws[buf][c0 + 3][r0] = rw0.w;       \
            Ws[buf][c0 + 0][r0 + 32] = rw1.x; Ws[buf][c0 + 1][r0 + 32] = rw1.y; \
            Ws[buf][c0 + 2][r0 + 32] = rw1.z; Ws[buf][c0 + 3][r0 + 32] = rw1.w; \
            Ws[buf][c0 + 0][r0 + 64] = rw2.x; Ws[buf][c0 + 1][r0 + 64] = rw2.y; \
            Ws[buf][c0 + 2][r0 + 64] = rw2.z; Ws[buf][c0 + 3][r0 + 64] = rw2.w; \
            Ws[buf][c0 + 0][r0 + 96] = rw3.x; Ws[buf][c0 + 1][r0 + 96] = rw3.y; \
            Ws[buf][c0 + 2][r0 + 96] = rw3.z; Ws[buf][c0 + 3][r0 + 96] = rw3.w; \
        }

    float acc[4][4] = {};
    LDG_TILE(0);
    STS_TILE(0);
    __syncthreads();

    #pragma unroll 1
    for (int kt = 0; kt < KTILES; kt++) {
        int cur = kt & 1;
        if (kt < KTILES - 1) { LDG_TILE((kt + 1) * BK); }
        #pragma unroll
        for (int k = 0; k < BK; k++) {
            float4 a0 = *(const float4*)&As[cur][k][tm];
            float4 w0 = *(const float4*)&Ws[cur][k][tn];
            float af[4] = {a0.x, a0.y, a0.z, a0.w};
            float wf[4] = {w0.x, w0.y, w0.z, w0.w};
            #pragma unroll
            for (int i = 0; i < 4; i++)
                #pragma unroll
                for (int j = 0; j < 4; j++)
                    acc[i][j] += af[i] * wf[j];
        }
        if (kt < KTILES - 1) {
            STS_TILE(cur ^ 1);
            __syncthreads();
        }
    }

    float bb[4], ac1[4], ac2[4];
    #pragma unroll
    for (int j = 0; j < 4; j++) {
        bb[j]  = b[tn + j];
        ac1[j] = ac_w[tn + j];
        ac2[j] = ac_w[OUT_F + tn + j];
    }
    #pragma unroll
    for (int i = 0; i < 4; i++) {
        int row = block_m + tm + i;
        float s1 = 0.f, s2 = 0.f;
        float4 hv;
        float* hp = (float*)&hv;
        #pragma unroll
        for (int j = 0; j < 4; j++) {
            float h = acc[i][j] + bb[j];
            hp[j] = h;
            s1 += h * ac1[j];
            s2 += h * ac2[j];
        }
        *(float4*)&g_hc[(size_t)row * OUT_F + tn] = hv;
        // warp covers all 128 columns for this row -> full reduction
        #pragma unroll
        for (int o = 16; o; o >>= 1) {
            s1 += __shfl_xor_sync(0xffffffffu, s1, o);
            s2 += __shfl_xor_sync(0xffffffffu, s2, o);
        }
        if (lane == 0) { g_sc_src[row] = s1; g_sd[row].x = s2; }
    }
}

// Per-row sparse masked softmax + weighted hc gather.
// Gather phase: 8 edge-partitions x 32 threads x float4 features.
__global__ void __launch_bounds__(256) k_attn(float* __restrict__ out,
                                              const float* __restrict__ Ws_coff,
                                              const float* __restrict__ Wc_coff) {
    __shared__ float wl[CAP];
    __shared__ unsigned short jl[CAP];
    __shared__ float red[32];
    __shared__ int s_cnt;
    __shared__ float pacc[8][OUT_F];   // per-partition partial sums

    int row = blockIdx.x;
    int tid = threadIdx.x;  // 256 threads, one bitmap word each
    int lane = tid & 31;
    int part = tid >> 5;    // 0..7
    float ca = fabsf(Ws_coff[0]);   // multiplies alpha_c (per reference)
    float cs = fabsf(Wc_coff[0]);   // multiplies alpha_s
    float sci = g_sc_src[row], ssi = g_ss_src[row];
    unsigned word = g_adj[row * NWORDS + tid];

    if (tid == 0) s_cnt = 0;
    if (row == 0 && tid == 1) g_isi32 = 0;   // reset detect flag for next replay
    __syncthreads();

    // pass 1: alpha per set bit -> smem list (guarded), track max
    int o = atomicAdd(&s_cnt, __popc(word));
    float m = -INFINITY;
    unsigned w = word;
    while (w) {
        int bpos = __ffs(w) - 1; w &= w - 1;
        int j = (tid << 5) + bpos;
        float2 sd = g_sd[j];
        float a = ca * lrelu(sci + sd.x) + cs * lrelu(ssi + sd.y);
        m = fmaxf(m, a);
        if (o < CAP) { wl[o] = a; jl[o] = (unsigned short)j; }
        o++;
    }
    m = blockReduceMax(m, red);   // syncs also finalize s_cnt and wl/jl
    int total = s_cnt;

    if (total == 0) {
        // masked row == all -9e15 -> uniform softmax -> mean of hc
        if (part == 0 || part == 1) {
            int f = tid & (OUT_F - 1);
            float acc = 0.f;
            for (int j = (tid >> 7); j < Nn; j += 2) acc += g_hc[(size_t)j * OUT_F + f];
            pacc[tid >> 7][f] = acc;
        }
        __syncthreads();
        if (tid < OUT_F)
            out[(size_t)row * OUT_F + tid] = (pacc[0][tid] + pacc[1][tid]) / (float)Nn;
        return;
    }

    if (total <= CAP) {
        // exp sweep over compacted smem list (no second gather)
        float zloc = 0.f;
        for (int k = tid; k < total; k += 256) {
            float e = __expf(wl[k] - m);
            wl[k] = e;
            zloc += e;
        }
        float Z = blockReduceSum(zloc, red);
        float inv = 1.f / Z;
        // float4 gather: partition `part` processes edges k = part, part+8, ...
        float a0 = 0.f, a1 = 0.f, a2 = 0.f, a3 = 0.f;
        #pragma unroll 2
        for (int k = part; k < total; k += 8) {
            float wv = wl[k];
            float4 h = *(const float4*)&g_hc[(size_t)jl[k] * OUT_F + lane * 4];
            a0 += wv * h.x; a1 += wv * h.y; a2 += wv * h.z; a3 += wv * h.w;
        }
        pacc[part][lane * 4 + 0] = a0;
        pacc[part][lane * 4 + 1] = a1;
        pacc[part][lane * 4 + 2] = a2;
        pacc[part][lane * 4 + 3] = a3;
        __syncthreads();
        if (tid < OUT_F) {
            float s = 0.f;
            #pragma unroll
            for (int p = 0; p < 8; p++) s += pacc[p][tid];
            out[(size_t)row * OUT_F + tid] = s * inv;
        }
        return;
    }

    // slow path (degree > CAP): recompute Z, then chunked compaction+gather
    {
        int f = tid & (OUT_F - 1);
        int half = tid >> 7;
        float zloc = 0.f;
        w = word;
        while (w) {
            int bpos = __ffs(w) - 1; w &= w - 1;
            int j = (tid << 5) + bpos;
            float2 sd = g_sd[j];
            float a = ca * lrelu(sci + sd.x) + cs * lrelu(ssi + sd.y);
            zloc += __expf(a - m);
        }
        float Z = blockReduceSum(zloc, red);
        float inv = 1.f / Z;
        float acc = 0.f;
        for (int c = 0; c < NWORDS / 32; c++) {
            __syncthreads();
            if (tid == 0) s_cnt = 0;
            __syncthreads();
            if (tid < 32) {
                unsigned wd = g_adj[row * NWORDS + c * 32 + tid];
                int oo = atomicAdd(&s_cnt, __popc(wd));
                while (wd) {
                    int bpos = __ffs(wd) - 1; wd &= wd - 1;
                    int j = ((c * 32 + tid) << 5) + bpos;
                    float2 sd = g_sd[j];
                    float a = ca * lrelu(sci + sd.x) + cs * lrelu(ssi + sd.y);
                    wl[oo] = __expf(a - m);
                    jl[oo] = (unsigned short)j;
                    oo++;
                }
            }
            __syncthreads();
            int cc = s_cnt;
            for (int k = half; k < cc; k += 2)
                acc += wl[k] * g_hc[(size_t)jl[k] * OUT_F + f];
        }
        pacc[half][f] = acc;
        __syncthreads();
        if (tid < OUT_F)
            out[(size_t)row * OUT_F + tid] = (pacc[0][tid] + pacc[1][tid]) * inv;
    }
}

// ---------------- launch ----------------
extern "C" void kernel_launch(void* const* d_in, const int* in_sizes, int n_in,
                              void* d_out, int out_size) {
    const float* h_context   = (const float*)d_in[0];
    const float* h_structure = (const float*)d_in[1];
    const int*   edge        = (const int*)d_in[2];   // int32 or int64, detected on device
    const float* Wc_w        = (const float*)d_in[3];
    const float* Wc_b        = (const float*)d_in[4];
    const float* Ws_w        = (const float*)d_in[5];
    const float* Ws_b        = (const float*)d_in[6];
    const float* ac_w        = (const float*)d_in[7];
    const float* as_w        = (const float*)d_in[8];
    const float* Ws_coff     = (const float*)d_in[9];
    const float* Wc_coff     = (const float*)d_in[10];
    float* out = (float*)d_out;
    int E = in_sizes[2] / 2;

    k_init<<<(Nn * NWORDS / 4) / 256, 256>>>(edge, E);
    k_edges<<<(E + 255) / 256, 256>>>(edge, E, Ws_w, Ws_b, as_w, Ws_coff, Wc_coff);
    k_sscore<<<(Nn * 32) / 256, 256>>>(h_structure);
    k_gemm<<<Nn / BM, 256>>>(h_context, Wc_w, Wc_b, ac_w);
    k_attn<<<Nn, 256>>>(out, Ws_coff, Wc_coff);
}

// round 7
// speedup vs baseline: 1.0957x; 1.0957x over previous
#include <cuda_runtime.h>
#include <math.h>

#define Nn 8192
#define IN_F 256
#define OUT_F 128
#define NWORDS 256   // bitmap words per row (8192 bits)
#define CAP 2048     // fast-path neighbor list capacity (expected degree ~32)

// ---------------- device scratch (no allocs allowed) ----------------
__device__ float    g_hc[Nn * OUT_F];          // 4 MB
__device__ unsigned g_adj[Nn * NWORDS];        // 8 MB adjacency bitmap
__device__ float    g_sc_src[Nn];
__device__ float    g_ss_src[Nn];
__device__ float2   g_sd[Nn];                  // (sc_dst, ss_dst) packed
__device__ float    g_vs1[IN_F], g_vs2[IN_F];  // hs-GEMM fold vectors
__device__ float    g_scal[4];                 // ca, cs, bs1, bs2
__device__ int      g_isi32 = 0;               // reset at end of k_attn

__device__ __forceinline__ float lrelu(float x) { return x > 0.f ? x : 0.01f * x; }

// packed f32x2 helpers (Blackwell FFMA2 path)
__device__ __forceinline__ void fma2(unsigned long long& d,
                                     unsigned long long a,
                                     unsigned long long w) {
    asm("fma.rn.f32x2 %0, %1, %2, %0;" : "+l"(d) : "l"(a), "l"(w));
}
__device__ __forceinline__ unsigned long long rep2(float x) {
    unsigned long long r;
    asm("mov.b64 %0, {%1, %1};" : "=l"(r) : "r"(__float_as_uint(x)));
    return r;
}
__device__ __forceinline__ void unpack2(unsigned long long v, float& lo, float& hi) {
    unsigned a, b;
    asm("mov.b64 {%0, %1}, %2;" : "=r"(a), "=r"(b) : "l"(v));
    lo = __uint_as_float(a);
    hi = __uint_as_float(b);
}

// ---------------- reductions (start and end with __syncthreads) ----------------
__device__ float blockReduceMax(float v, float* red) {
    __syncthreads();
    #pragma unroll
    for (int o = 16; o; o >>= 1) v = fmaxf(v, __shfl_xor_sync(0xffffffffu, v, o));
    int w = threadIdx.x >> 5;
    if ((threadIdx.x & 31) == 0) red[w] = v;
    __syncthreads();
    if (threadIdx.x < 32) {
        float x = (threadIdx.x < (blockDim.x >> 5)) ? red[threadIdx.x] : -INFINITY;
        #pragma unroll
        for (int o = 4; o; o >>= 1) x = fmaxf(x, __shfl_xor_sync(0xffffffffu, x, o));
        if (threadIdx.x == 0) red[0] = x;
    }
    __syncthreads();
    return red[0];
}

__device__ float blockReduceSum(float v, float* red) {
    __syncthreads();
    #pragma unroll
    for (int o = 16; o; o >>= 1) v += __shfl_xor_sync(0xffffffffu, v, o);
    int w = threadIdx.x >> 5;
    if ((threadIdx.x & 31) == 0) red[w] = v;
    __syncthreads();
    if (threadIdx.x < 32) {
        float x = (threadIdx.x < (blockDim.x >> 5)) ? red[threadIdx.x] : 0.f;
        #pragma unroll
        for (int o = 4; o; o >>= 1) x += __shfl_xor_sync(0xffffffffu, x, o);
        if (threadIdx.x == 0) red[0] = x;
    }
    __syncthreads();
    return red[0];
}

// ---------------- kernels ----------------
// Fused: vectorized bitmap clear + int32/int64 detection + g_vs zero (block 0).
__global__ void k_init(const int* __restrict__ p32, int E) {
    int i = blockIdx.x * blockDim.x + threadIdx.x;
    ((uint4*)g_adj)[i] = make_uint4(0u, 0u, 0u, 0u);
    if (blockIdx.x == 0) {
        g_vs1[threadIdx.x] = 0.f;
        g_vs2[threadIdx.x] = 0.f;
    }
    if (i < E) {
        if (p32[2 * i + 1] != 0) atomicOr(&g_isi32, 1);
    }
}

// Edge bitmap build; blocks 0..7 also accumulate the hs-GEMM fold
// (vs = Ws_w^T @ as_half) via coalesced partials + atomicAdd; block 8 does
// bias dots + coefficient abs.
__global__ void k_edges(const int* __restrict__ p32, int E,
                        const float* __restrict__ Ws_w,
                        const float* __restrict__ Ws_b,
                        const float* __restrict__ as_w,
                        const float* __restrict__ Ws_coff,
                        const float* __restrict__ Wc_coff) {
    int tid = threadIdx.x;
    int e = blockIdx.x * blockDim.x + tid;
    if (e < E) {
        int r, c;
        if (g_isi32) {
            r = p32[e];
            c = p32[E + e];
        } else {
            const long long* p64 = (const long long*)p32;
            r = (int)p64[e];
            c = (int)p64[E + e];
        }
        if ((unsigned)r < Nn && (unsigned)c < Nn)
            atomicOr(&g_adj[r * NWORDS + (c >> 5)], 1u << (c & 31));
    }
    if (blockIdx.x < 8) {
        float v1 = 0.f, v2 = 0.f;
        #pragma unroll
        for (int i = 0; i < 16; i++) {
            int f = blockIdx.x * 16 + i;
            float w = Ws_w[f * IN_F + tid];
            v1 += w * as_w[f];
            v2 += w * as_w[OUT_F + f];
        }
        atomicAdd(&g_vs1[tid], v1);
        atomicAdd(&g_vs2[tid], v2);
    } else if (blockIdx.x == 8 && tid < 32) {
        float b1 = 0.f, b2 = 0.f;
        #pragma unroll
        for (int i = 0; i < 4; i++) {
            int f = tid + 32 * i;
            float wb = Ws_b[f];
            b1 += wb * as_w[f];
            b2 += wb * as_w[OUT_F + f];
        }
        #pragma unroll
        for (int o = 16; o; o >>= 1) {
            b1 += __shfl_xor_sync(0xffffffffu, b1, o);
            b2 += __shfl_xor_sync(0xffffffffu, b2, o);
        }
        if (tid == 0) {
            g_scal[0] = fabsf(Ws_coff[0]);  // multiplies alpha_c
            g_scal[1] = fabsf(Wc_coff[0]);  // multiplies alpha_s
            g_scal[2] = b1;
            g_scal[3] = b2;
        }
    }
}

// Structure scores: warp per row, softmax over 256 features dotted with g_vs.
__global__ void k_sscore(const float* __restrict__ hstruct) {
    int warp = (blockIdx.x * blockDim.x + threadIdx.x) >> 5;
    int lane = threadIdx.x & 31;
    if (warp >= Nn) return;
    const float* x = hstruct + (size_t)warp * IN_F;
    float v[8], w1[8], w2[8];
    float m = -INFINITY;
    #pragma unroll
    for (int e = 0; e < 8; e++) {
        v[e]  = x[lane + 32 * e];
        w1[e] = g_vs1[lane + 32 * e];
        w2[e] = g_vs2[lane + 32 * e];
        m = fmaxf(m, v[e]);
    }
    #pragma unroll
    for (int o = 16; o; o >>= 1) m = fmaxf(m, __shfl_xor_sync(0xffffffffu, m, o));
    float z = 0.f, d1 = 0.f, d2 = 0.f;
    #pragma unroll
    for (int e = 0; e < 8; e++) {
        float ex = __expf(v[e] - m);
        z  += ex;
        d1 += ex * w1[e];
        d2 += ex * w2[e];
    }
    #pragma unroll
    for (int o = 16; o; o >>= 1) {
        z  += __shfl_xor_sync(0xffffffffu, z,  o);
        d1 += __shfl_xor_sync(0xffffffffu, d1, o);
        d2 += __shfl_xor_sync(0xffffffffu, d2, o);
    }
    if (lane == 0) {
        g_ss_src[warp] = d1 / z + g_scal[2];
        g_sd[warp].y   = d2 / z + g_scal[3];
    }
}

// hc = h_context @ Wc_w^T + Wc_b  (M=8192, N=128, K=256) fp32 SGEMM,
// double-buffered smem, FFMA2 (packed f32x2) inner loop, fused score epilogue.
#define BM 64
#define BN 128
#define BK 32
#define KTILES (IN_F / BK)
__global__ void __launch_bounds__(256) k_gemm(const float* __restrict__ A,
                                              const float* __restrict__ W,
                                              const float* __restrict__ b,
                                              const float* __restrict__ ac_w) {
    __shared__ __align__(16) float As[2][BK][BM + 4];
    __shared__ __align__(16) float Ws[2][BK][BN + 4];
    int tid = threadIdx.x;
    int lane = tid & 31;
    int block_m = blockIdx.x * BM;
    int tn = lane * 4;         // 0..124
    int tm = (tid >> 5) * 8;   // 0..56 (warp-uniform -> As loads broadcast)

    int r0 = tid >> 3;             // 0..31
    int c0 = (tid & 7) * 4;
    const float* Aptr0 = &A[(size_t)(block_m + r0) * IN_F + c0];
    const float* Aptr1 = Aptr0 + (size_t)32 * IN_F;
    const float* Wptr  = &W[(size_t)r0 * IN_F + c0];

    float4 ra0, ra1, rw0, rw1, rw2, rw3;
    #define LDG_TILE(k0)                                                    \
        ra0 = *(const float4*)(Aptr0 + (k0));                               \
        ra1 = *(const float4*)(Aptr1 + (k0));                               \
        rw0 = *(const float4*)(Wptr + (k0));                                \
        rw1 = *(const float4*)(Wptr + (size_t)32 * IN_F + (k0));            \
        rw2 = *(const float4*)(Wptr + (size_t)64 * IN_F + (k0));            \
        rw3 = *(const float4*)(Wptr + (size_t)96 * IN_F + (k0));

    #define STS_TILE(buf)                                                   \
        {                                                                   \
            As[buf][c0 + 0][r0] = ra0.x; As[buf][c0 + 1][r0] = ra0.y;       \
            As[buf][c0 + 2][r0] = ra0.z; As[buf][c0 + 3][r0] = ra0.w;       \
            As[buf][c0 + 0][r0 + 32] = ra1.x; As[buf][c0 + 1][r0 + 32] = ra1.y; \
            As[buf][c0 + 2][r0 + 32] = ra1.z; As[buf][c0 + 3][r0 + 32] = ra1.w; \
            Ws[buf][c0 + 0][r0] = rw0.x; Ws[buf][c0 + 1][r0] = rw0.y;       \
            Ws[buf][c0 + 2][r0] = rw0.z; Ws[buf][c0 + 3][r0] = rw0.w;       \
            Ws[buf][c0 + 0][r0 + 32] = rw1.x; Ws[buf][c0 + 1][r0 + 32] = rw1.y; \
            Ws[buf][c0 + 2][r0 + 32] = rw1.z; Ws[buf][c0 + 3][r0 + 32] = rw1.w; \
            Ws[buf][c0 + 0][r0 + 64] = rw2.x; Ws[buf][c0 + 1][r0 + 64] = rw2.y; \
            Ws[buf][c0 + 2][r0 + 64] = rw2.z; Ws[buf][c0 + 3][r0 + 64] = rw2.w; \
            Ws[buf][c0 + 0][r0 + 96] = rw3.x; Ws[buf][c0 + 1][r0 + 96] = rw3.y; \
            Ws[buf][c0 + 2][r0 + 96] = rw3.z; Ws[buf][c0 + 3][r0 + 96] = rw3.w; \
        }

    // acc2[p][j]: row-pair p (rows tm+2p, tm+2p+1), column tn+j, packed f32x2
    unsigned long long acc2[4][4] = {};
    LDG_TILE(0);
    STS_TILE(0);
    __syncthreads();

    #pragma unroll 1
    for (int kt = 0; kt < KTILES; kt++) {
        int cur = kt & 1;
        if (kt < KTILES - 1) { LDG_TILE((kt + 1) * BK); }
        #pragma unroll
        for (int k = 0; k < BK; k++) {
            // A rows tm..tm+7 as 4 ready-packed f32x2 (LDS.128, warp-broadcast)
            ulonglong2 aA = *(const ulonglong2*)&As[cur][k][tm];
            ulonglong2 aB = *(const ulonglong2*)&As[cur][k][tm + 4];
            float4 w0 = *(const float4*)&Ws[cur][k][tn];
            unsigned long long ap[4] = {aA.x, aA.y, aB.x, aB.y};
            unsigned long long ww[4] = {rep2(w0.x), rep2(w0.y), rep2(w0.z), rep2(w0.w)};
            #pragma unroll
            for (int p = 0; p < 4; p++) {
                fma2(acc2[p][0], ap[p], ww[0]);
                fma2(acc2[p][1], ap[p], ww[1]);
                fma2(acc2[p][2], ap[p], ww[2]);
                fma2(acc2[p][3], ap[p], ww[3]);
            }
        }
        if (kt < KTILES - 1) {
            STS_TILE(cur ^ 1);
            __syncthreads();
        }
    }

    // unpack to accf[8][4]
    float accf[8][4];
    #pragma unroll
    for (int p = 0; p < 4; p++)
        #pragma unroll
        for (int j = 0; j < 4; j++)
            unpack2(acc2[p][j], accf[2 * p][j], accf[2 * p + 1][j]);

    float bb[4], ac1[4], ac2[4];
    #pragma unroll
    for (int j = 0; j < 4; j++) {
        bb[j]  = b[tn + j];
        ac1[j] = ac_w[tn + j];
        ac2[j] = ac_w[OUT_F + tn + j];
    }
    #pragma unroll
    for (int i = 0; i < 8; i++) {
        int row = block_m + tm + i;
        float s1 = 0.f, s2 = 0.f;
        float4 hv;
        float* hp = (float*)&hv;
        #pragma unroll
        for (int j = 0; j < 4; j++) {
            float h = accf[i][j] + bb[j];
            hp[j] = h;
            s1 += h * ac1[j];
            s2 += h * ac2[j];
        }
        *(float4*)&g_hc[(size_t)row * OUT_F + tn] = hv;
        #pragma unroll
        for (int o = 16; o; o >>= 1) {
            s1 += __shfl_xor_sync(0xffffffffu, s1, o);
            s2 += __shfl_xor_sync(0xffffffffu, s2, o);
        }
        if (lane == 0) { g_sc_src[row] = s1; g_sd[row].x = s2; }
    }
}

// Per-row sparse masked softmax + weighted hc gather.
// Gather phase: 8 edge-partitions x 32 threads x float4 features.
__global__ void __launch_bounds__(256) k_attn(float* __restrict__ out,
                                              const float* __restrict__ Ws_coff,
                                              const float* __restrict__ Wc_coff) {
    __shared__ float wl[CAP];
    __shared__ unsigned short jl[CAP];
    __shared__ float red[32];
    __shared__ int s_cnt;
    __shared__ float pacc[8][OUT_F];   // per-partition partial sums

    int row = blockIdx.x;
    int tid = threadIdx.x;  // 256 threads, one bitmap word each
    int lane = tid & 31;
    int part = tid >> 5;    // 0..7
    float ca = fabsf(Ws_coff[0]);   // multiplies alpha_c (per reference)
    float cs = fabsf(Wc_coff[0]);   // multiplies alpha_s
    float sci = g_sc_src[row], ssi = g_ss_src[row];
    unsigned word = g_adj[row * NWORDS + tid];

    if (tid == 0) s_cnt = 0;
    if (row == 0 && tid == 1) g_isi32 = 0;   // reset detect flag for next replay
    __syncthreads();

    // pass 1: alpha per set bit -> smem list (guarded), track max
    int o = atomicAdd(&s_cnt, __popc(word));
    float m = -INFINITY;
    unsigned w = word;
    while (w) {
        int bpos = __ffs(w) - 1; w &= w - 1;
        int j = (tid << 5) + bpos;
        float2 sd = g_sd[j];
        float a = ca * lrelu(sci + sd.x) + cs * lrelu(ssi + sd.y);
        m = fmaxf(m, a);
        if (o < CAP) { wl[o] = a; jl[o] = (unsigned short)j; }
        o++;
    }
    m = blockReduceMax(m, red);   // syncs also finalize s_cnt and wl/jl
    int total = s_cnt;

    if (total == 0) {
        // masked row == all -9e15 -> uniform softmax -> mean of hc
        if (part == 0 || part == 1) {
            int f = tid & (OUT_F - 1);
            float acc = 0.f;
            for (int j = (tid >> 7); j < Nn; j += 2) acc += g_hc[(size_t)j * OUT_F + f];
            pacc[tid >> 7][f] = acc;
        }
        __syncthreads();
        if (tid < OUT_F)
            out[(size_t)row * OUT_F + tid] = (pacc[0][tid] + pacc[1][tid]) / (float)Nn;
        return;
    }

    if (total <= CAP) {
        // exp sweep over compacted smem list (no second gather)
        float zloc = 0.f;
        for (int k = tid; k < total; k += 256) {
            float e = __expf(wl[k] - m);
            wl[k] = e;
            zloc += e;
        }
        float Z = blockReduceSum(zloc, red);
        float inv = 1.f / Z;
        // float4 gather: partition `part` processes edges k = part, part+8, ...
        float a0 = 0.f, a1 = 0.f, a2 = 0.f, a3 = 0.f;
        #pragma unroll 2
        for (int k = part; k < total; k += 8) {
            float wv = wl[k];
            float4 h = *(const float4*)&g_hc[(size_t)jl[k] * OUT_F + lane * 4];
            a0 += wv * h.x; a1 += wv * h.y; a2 += wv * h.z; a3 += wv * h.w;
        }
        pacc[part][lane * 4 + 0] = a0;
        pacc[part][lane * 4 + 1] = a1;
        pacc[part][lane * 4 + 2] = a2;
        pacc[part][lane * 4 + 3] = a3;
        __syncthreads();
        if (tid < OUT_F) {
            float s = 0.f;
            #pragma unroll
            for (int p = 0; p < 8; p++) s += pacc[p][tid];
            out[(size_t)row * OUT_F + tid] = s * inv;
        }
        return;
    }

    // slow path (degree > CAP): recompute Z, then chunked compaction+gather
    {
        int f = tid & (OUT_F - 1);
        int half = tid >> 7;
        float zloc = 0.f;
        w = word;
        while (w) {
            int bpos = __ffs(w) - 1; w &= w - 1;
            int j = (tid << 5) + bpos;
            float2 sd = g_sd[j];
            float a = ca * lrelu(sci + sd.x) + cs * lrelu(ssi + sd.y);
            zloc += __expf(a - m);
        }
        float Z = blockReduceSum(zloc, red);
        float inv = 1.f / Z;
        float acc = 0.f;
        for (int c = 0; c < NWORDS / 32; c++) {
            __syncthreads();
            if (tid == 0) s_cnt = 0;
            __syncthreads();
            if (tid < 32) {
                unsigned wd = g_adj[row * NWORDS + c * 32 + tid];
                int oo = atomicAdd(&s_cnt, __popc(wd));
                while (wd) {
                    int bpos = __ffs(wd) - 1; wd &= wd - 1;
                    int j = ((c * 32 + tid) << 5) + bpos;
                    float2 sd = g_sd[j];
                    float a = ca * lrelu(sci + sd.x) + cs * lrelu(ssi + sd.y);
                    wl[oo] = __expf(a - m);
                    jl[oo] = (unsigned short)j;
                    oo++;
                }
            }
            __syncthreads();
            int cc = s_cnt;
            for (int k = half; k < cc; k += 2)
                acc += wl[k] * g_hc[(size_t)jl[k] * OUT_F + f];
        }
        pacc[half][f] = acc;
        __syncthreads();
        if (tid < OUT_F)
            out[(size_t)row * OUT_F + tid] = (pacc[0][tid] + pacc[1][tid]) * inv;
    }
}

// ---------------- launch ----------------
extern "C" void kernel_launch(void* const* d_in, const int* in_sizes, int n_in,
                              void* d_out, int out_size) {
    const float* h_context   = (const float*)d_in[0];
    const float* h_structure = (const float*)d_in[1];
    const int*   edge        = (const int*)d_in[2];   // int32 or int64, detected on device
    const float* Wc_w        = (const float*)d_in[3];
    const float* Wc_b        = (const float*)d_in[4];
    const float* Ws_w        = (const float*)d_in[5];
    const float* Ws_b        = (const float*)d_in[6];
    const float* ac_w        = (const float*)d_in[7];
    const float* as_w        = (const float*)d_in[8];
    const float* Ws_coff     = (const float*)d_in[9];
    const float* Wc_coff     = (const float*)d_in[10];
    float* out = (float*)d_out;
    int E = in_sizes[2] / 2;

    k_init<<<(Nn * NWORDS / 4) / 256, 256>>>(edge, E);
    k_edges<<<(E + 255) / 256, 256>>>(edge, E, Ws_w, Ws_b, as_w, Ws_coff, Wc_coff);
    k_sscore<<<(Nn * 32) / 256, 256>>>(h_structure);
    k_gemm<<<Nn / BM, 256>>>(h_context, Wc_w, Wc_b, ac_w);
    k_attn<<<Nn, 256>>>(out, Ws_coff, Wc_coff);
}

// round 8
// speedup vs baseline: 1.1708x; 1.0685x over previous
#include <cuda_runtime.h>
#include <cuda_bf16.h>
#include <math.h>

#define Nn 8192
#define IN_F 256
#define OUT_F 128
#define NWORDS 256   // bitmap words per row (8192 bits)
#define CAP 2048     // fast-path neighbor list capacity (expected degree ~32)

// ---------------- device scratch (no allocs allowed) ----------------
__device__ float    g_hc[Nn * OUT_F];          // 4 MB
__device__ unsigned g_adj[Nn * NWORDS];        // 8 MB adjacency bitmap
__device__ float    g_sc_src[Nn];
__device__ float    g_ss_src[Nn];
__device__ float2   g_sd[Nn];                  // (sc_dst, ss_dst) packed
__device__ float    g_vs1[IN_F], g_vs2[IN_F];  // hs-GEMM fold vectors
__device__ float    g_scal[4];                 // ca, cs, bs1, bs2
__device__ int      g_isi32 = 0;               // reset at end of k_attn

__device__ __forceinline__ float lrelu(float x) { return x > 0.f ? x : 0.01f * x; }

// ---------------- reductions (start and end with __syncthreads) ----------------
__device__ float blockReduceMax(float v, float* red) {
    __syncthreads();
    #pragma unroll
    for (int o = 16; o; o >>= 1) v = fmaxf(v, __shfl_xor_sync(0xffffffffu, v, o));
    int w = threadIdx.x >> 5;
    if ((threadIdx.x & 31) == 0) red[w] = v;
    __syncthreads();
    if (threadIdx.x < 32) {
        float x = (threadIdx.x < (blockDim.x >> 5)) ? red[threadIdx.x] : -INFINITY;
        #pragma unroll
        for (int o = 4; o; o >>= 1) x = fmaxf(x, __shfl_xor_sync(0xffffffffu, x, o));
        if (threadIdx.x == 0) red[0] = x;
    }
    __syncthreads();
    return red[0];
}

__device__ float blockReduceSum(float v, float* red) {
    __syncthreads();
    #pragma unroll
    for (int o = 16; o; o >>= 1) v += __shfl_xor_sync(0xffffffffu, v, o);
    int w = threadIdx.x >> 5;
    if ((threadIdx.x & 31) == 0) red[w] = v;
    __syncthreads();
    if (threadIdx.x < 32) {
        float x = (threadIdx.x < (blockDim.x >> 5)) ? red[threadIdx.x] : 0.f;
        #pragma unroll
        for (int o = 4; o; o >>= 1) x += __shfl_xor_sync(0xffffffffu, x, o);
        if (threadIdx.x == 0) red[0] = x;
    }
    __syncthreads();
    return red[0];
}

// ---------------- kernels ----------------
// Fused: vectorized bitmap clear + int32/int64 detection + g_vs zero (block 0).
__global__ void k_init(const int* __restrict__ p32, int E) {
    int i = blockIdx.x * blockDim.x + threadIdx.x;
    ((uint4*)g_adj)[i] = make_uint4(0u, 0u, 0u, 0u);
    if (blockIdx.x == 0) {
        g_vs1[threadIdx.x] = 0.f;
        g_vs2[threadIdx.x] = 0.f;
    }
    if (i < E) {
        if (p32[2 * i + 1] != 0) atomicOr(&g_isi32, 1);
    }
}

// Edge bitmap build; blocks 0..7 also accumulate the hs-GEMM fold; block 8
// does bias dots + coefficient abs.
__global__ void k_edges(const int* __restrict__ p32, int E,
                        const float* __restrict__ Ws_w,
                        const float* __restrict__ Ws_b,
                        const float* __restrict__ as_w,
                        const float* __restrict__ Ws_coff,
                        const float* __restrict__ Wc_coff) {
    int tid = threadIdx.x;
    int e = blockIdx.x * blockDim.x + tid;
    if (e < E) {
        int r, c;
        if (g_isi32) {
            r = p32[e];
            c = p32[E + e];
        } else {
            const long long* p64 = (const long long*)p32;
            r = (int)p64[e];
            c = (int)p64[E + e];
        }
        if ((unsigned)r < Nn && (unsigned)c < Nn)
            atomicOr(&g_adj[r * NWORDS + (c >> 5)], 1u << (c & 31));
    }
    if (blockIdx.x < 8) {
        float v1 = 0.f, v2 = 0.f;
        #pragma unroll
        for (int i = 0; i < 16; i++) {
            int f = blockIdx.x * 16 + i;
            float w = Ws_w[f * IN_F + tid];
            v1 += w * as_w[f];
            v2 += w * as_w[OUT_F + f];
        }
        atomicAdd(&g_vs1[tid], v1);
        atomicAdd(&g_vs2[tid], v2);
    } else if (blockIdx.x == 8 && tid < 32) {
        float b1 = 0.f, b2 = 0.f;
        #pragma unroll
        for (int i = 0; i < 4; i++) {
            int f = tid + 32 * i;
            float wb = Ws_b[f];
            b1 += wb * as_w[f];
            b2 += wb * as_w[OUT_F + f];
        }
        #pragma unroll
        for (int o = 16; o; o >>= 1) {
            b1 += __shfl_xor_sync(0xffffffffu, b1, o);
            b2 += __shfl_xor_sync(0xffffffffu, b2, o);
        }
        if (tid == 0) {
            g_scal[0] = fabsf(Ws_coff[0]);  // multiplies alpha_c
            g_scal[1] = fabsf(Wc_coff[0]);  // multiplies alpha_s
            g_scal[2] = b1;
            g_scal[3] = b2;
        }
    }
}

// Structure scores: warp per row, softmax over 256 features dotted with g_vs.
__global__ void k_sscore(const float* __restrict__ hstruct) {
    int warp = (blockIdx.x * blockDim.x + threadIdx.x) >> 5;
    int lane = threadIdx.x & 31;
    if (warp >= Nn) return;
    const float* x = hstruct + (size_t)warp * IN_F;
    float v[8], w1[8], w2[8];
    float m = -INFINITY;
    #pragma unroll
    for (int e = 0; e < 8; e++) {
        v[e]  = x[lane + 32 * e];
        w1[e] = g_vs1[lane + 32 * e];
        w2[e] = g_vs2[lane + 32 * e];
        m = fmaxf(m, v[e]);
    }
    #pragma unroll
    for (int o = 16; o; o >>= 1) m = fmaxf(m, __shfl_xor_sync(0xffffffffu, m, o));
    float z = 0.f, d1 = 0.f, d2 = 0.f;
    #pragma unroll
    for (int e = 0; e < 8; e++) {
        float ex = __expf(v[e] - m);
        z  += ex;
        d1 += ex * w1[e];
        d2 += ex * w2[e];
    }
    #pragma unroll
    for (int o = 16; o; o >>= 1) {
        z  += __shfl_xor_sync(0xffffffffu, z,  o);
        d1 += __shfl_xor_sync(0xffffffffu, d1, o);
        d2 += __shfl_xor_sync(0xffffffffu, d2, o);
    }
    if (lane == 0) {
        g_ss_src[warp] = d1 / z + g_scal[2];
        g_sd[warp].y   = d2 / z + g_scal[3];
    }
}

// ---------------- split-bf16 tensor-core GEMM ----------------
// hc = h_context @ Wc_w^T + Wc_b via mma.sync m16n8k16 bf16:
//   a*b ~= a_hi*b_hi + a_hi*b_lo + a_lo*b_hi   (fp32 accumulate)
// BM=64 rows/block, all N=128, K chunks of 32. 256 threads = 8 warps
// laid out 4(m16) x 2(n64). Fused bias + context-score epilogue.
#define BM 64
#define BK 32
#define KCHUNKS (IN_F / BK)
#define APAD 40   // bf16 elems per row in smem (32 + 8 pad) -> 20-word stride

__device__ __forceinline__ void mma_bf16(float* c, const unsigned* a,
                                         unsigned b0, unsigned b1) {
    asm volatile(
        "mma.sync.aligned.m16n8k16.row.col.f32.bf16.bf16.f32 "
        "{%0,%1,%2,%3}, {%4,%5,%6,%7}, {%8,%9}, {%0,%1,%2,%3};"
        : "+f"(c[0]), "+f"(c[1]), "+f"(c[2]), "+f"(c[3])
        : "r"(a[0]), "r"(a[1]), "r"(a[2]), "r"(a[3]), "r"(b0), "r"(b1));
}

__device__ __forceinline__ void split4(float4 v, __nv_bfloat16* hi, __nv_bfloat16* lo) {
    float xs[4] = {v.x, v.y, v.z, v.w};
    #pragma unroll
    for (int i = 0; i < 4; i++) {
        __nv_bfloat16 h = __float2bfloat16(xs[i]);
        hi[i] = h;
        lo[i] = __float2bfloat16(xs[i] - __bfloat162float(h));
    }
}

__global__ void __launch_bounds__(256) k_gemm(const float* __restrict__ A,
                                              const float* __restrict__ W,
                                              const float* __restrict__ b,
                                              const float* __restrict__ ac_w) {
    __shared__ __nv_bfloat16 A_s[2][BM][APAD];      // [plane][row][k]  10.2 KB
    __shared__ __nv_bfloat16 W_s[2][OUT_F][APAD];   // [plane][n][k]    20.5 KB
    __shared__ float p_s1[8][16], p_s2[8][16];

    int tid = threadIdx.x;
    int lane = tid & 31;
    int warp = tid >> 5;
    int block_m = blockIdx.x * BM;
    int mrow = (warp >> 1) * 16;     // 0,16,32,48
    int nbase = (warp & 1) * 64;     // 0 or 64
    int g  = lane >> 2;              // 0..7
    int t4 = lane & 3;               // 0..3

    // LDG indices for staging (row-contiguous, fully coalesced)
    int arow = tid >> 3;             // 0..31
    int akc  = (tid & 7) * 4;        // 0,4,..28 within chunk
    float acc[8][4] = {};

    float4 ra0, ra1, rw0, rw1, rw2, rw3;
    #define GLD(c0_)                                                          \
        ra0 = *(const float4*)&A[(size_t)(block_m + arow) * IN_F + (c0_) + akc];      \
        ra1 = *(const float4*)&A[(size_t)(block_m + arow + 32) * IN_F + (c0_) + akc]; \
        rw0 = *(const float4*)&W[(size_t)arow * IN_F + (c0_) + akc];                  \
        rw1 = *(const float4*)&W[(size_t)(arow + 32) * IN_F + (c0_) + akc];           \
        rw2 = *(const float4*)&W[(size_t)(arow + 64) * IN_F + (c0_) + akc];           \
        rw3 = *(const float4*)&W[(size_t)(arow + 96) * IN_F + (c0_) + akc];

    GLD(0);

    #pragma unroll 1
    for (int c = 0; c < KCHUNKS; c++) {
        // stage chunk into smem (f32 -> bf16 hi/lo planes)
        split4(ra0, &A_s[0][arow][akc],      &A_s[1][arow][akc]);
        split4(ra1, &A_s[0][arow + 32][akc], &A_s[1][arow + 32][akc]);
        split4(rw0, &W_s[0][arow][akc],      &W_s[1][arow][akc]);
        split4(rw1, &W_s[0][arow + 32][akc], &W_s[1][arow + 32][akc]);
        split4(rw2, &W_s[0][arow + 64][akc], &W_s[1][arow + 64][akc]);
        split4(rw3, &W_s[0][arow + 96][akc], &W_s[1][arow + 96][akc]);
        __syncthreads();
        if (c < KCHUNKS - 1) { GLD((c + 1) * BK); }

        #pragma unroll
        for (int ks = 0; ks < 2; ks++) {
            int kb = ks * 16 + 2 * t4;   // element offset of this lane's k-pair
            unsigned ah[4], al[4];
            ah[0] = *(const unsigned*)&A_s[0][mrow + g][kb];
            ah[1] = *(const unsigned*)&A_s[0][mrow + g + 8][kb];
            ah[2] = *(const unsigned*)&A_s[0][mrow + g][kb + 8];
            ah[3] = *(const unsigned*)&A_s[0][mrow + g + 8][kb + 8];
            al[0] = *(const unsigned*)&A_s[1][mrow + g][kb];
            al[1] = *(const unsigned*)&A_s[1][mrow + g + 8][kb];
            al[2] = *(const unsigned*)&A_s[1][mrow + g][kb + 8];
            al[3] = *(const unsigned*)&A_s[1][mrow + g + 8][kb + 8];
            #pragma unroll
            for (int t = 0; t < 8; t++) {
                int n = nbase + 8 * t + g;
                unsigned bh0 = *(const unsigned*)&W_s[0][n][kb];
                unsigned bh1 = *(const unsigned*)&W_s[0][n][kb + 8];
                unsigned bl0 = *(const unsigned*)&W_s[1][n][kb];
                unsigned bl1 = *(const unsigned*)&W_s[1][n][kb + 8];
                mma_bf16(acc[t], ah, bh0, bh1);
                mma_bf16(acc[t], ah, bl0, bl1);
                mma_bf16(acc[t], al, bh0, bh1);
            }
        }
        __syncthreads();
    }

    // epilogue: bias add, hc store, fused context scores
    // lane holds rows (mrow+g, mrow+g+8), cols nbase+8t+2*t4+{0,1}
    float s1g = 0.f, s1h = 0.f, s2g = 0.f, s2h = 0.f;
    int row0 = block_m + mrow + g;
    #pragma unroll
    for (int t = 0; t < 8; t++) {
        int col = nbase + 8 * t + 2 * t4;
        float2 bb  = *(const float2*)&b[col];
        float2 w1v = *(const float2*)&ac_w[col];
        float2 w2v = *(const float2*)&ac_w[OUT_F + col];
        float c0 = acc[t][0] + bb.x;
        float c1 = acc[t][1] + bb.y;
        float c2 = acc[t][2] + bb.x;
        float c3 = acc[t][3] + bb.y;
        *(float2*)&g_hc[(size_t)row0 * OUT_F + col]       = make_float2(c0, c1);
        *(float2*)&g_hc[(size_t)(row0 + 8) * OUT_F + col] = make_float2(c2, c3);
        s1g += c0 * w1v.x + c1 * w1v.y;
        s1h += c2 * w1v.x + c3 * w1v.y;
        s2g += c0 * w2v.x + c1 * w2v.y;
        s2h += c2 * w2v.x + c3 * w2v.y;
    }
    // reduce over the 4 lanes of the quad (t4)
    #pragma unroll
    for (int o = 1; o <= 2; o <<= 1) {
        s1g += __shfl_xor_sync(0xffffffffu, s1g, o);
        s1h += __shfl_xor_sync(0xffffffffu, s1h, o);
        s2g += __shfl_xor_sync(0xffffffffu, s2g, o);
        s2h += __shfl_xor_sync(0xffffffffu, s2h, o);
    }
    if (t4 == 0) {
        p_s1[warp][g] = s1g;  p_s1[warp][g + 8] = s1h;
        p_s2[warp][g] = s2g;  p_s2[warp][g + 8] = s2h;
    }
    __syncthreads();
    if (tid < BM) {
        int mt = tid >> 4, r = tid & 15;
        int row = block_m + mt * 16 + r;
        g_sc_src[row] = p_s1[2 * mt][r] + p_s1[2 * mt + 1][r];
        g_sd[row].x   = p_s2[2 * mt][r] + p_s2[2 * mt + 1][r];
    }
}

// Per-row sparse masked softmax + weighted hc gather.
__global__ void __launch_bounds__(256) k_attn(float* __restrict__ out,
                                              const float* __restrict__ Ws_coff,
                                              const float* __restrict__ Wc_coff) {
    __shared__ float wl[CAP];
    __shared__ unsigned short jl[CAP];
    __shared__ float red[32];
    __shared__ int s_cnt;
    __shared__ float pacc[8][OUT_F];

    int row = blockIdx.x;
    int tid = threadIdx.x;
    int lane = tid & 31;
    int part = tid >> 5;    // 0..7
    float ca = fabsf(Ws_coff[0]);   // multiplies alpha_c (per reference)
    float cs = fabsf(Wc_coff[0]);   // multiplies alpha_s
    float sci = g_sc_src[row], ssi = g_ss_src[row];
    unsigned word = g_adj[row * NWORDS + tid];

    if (tid == 0) s_cnt = 0;
    if (row == 0 && tid == 1) g_isi32 = 0;
    __syncthreads();

    int o = atomicAdd(&s_cnt, __popc(word));
    float m = -INFINITY;
    unsigned w = word;
    while (w) {
        int bpos = __ffs(w) - 1; w &= w - 1;
        int j = (tid << 5) + bpos;
        float2 sd = g_sd[j];
        float a = ca * lrelu(sci + sd.x) + cs * lrelu(ssi + sd.y);
        m = fmaxf(m, a);
        if (o < CAP) { wl[o] = a; jl[o] = (unsigned short)j; }
        o++;
    }
    m = blockReduceMax(m, red);
    int total = s_cnt;

    if (total == 0) {
        if (part == 0 || part == 1) {
            int f = tid & (OUT_F - 1);
            float acc = 0.f;
            for (int j = (tid >> 7); j < Nn; j += 2) acc += g_hc[(size_t)j * OUT_F + f];
            pacc[tid >> 7][f] = acc;
        }
        __syncthreads();
        if (tid < OUT_F)
            out[(size_t)row * OUT_F + tid] = (pacc[0][tid] + pacc[1][tid]) / (float)Nn;
        return;
    }

    if (total <= CAP) {
        float zloc = 0.f;
        for (int k = tid; k < total; k += 256) {
            float e = __expf(wl[k] - m);
            wl[k] = e;
            zloc += e;
        }
        float Z = blockReduceSum(zloc, red);
        float inv = 1.f / Z;
        float a0 = 0.f, a1 = 0.f, a2 = 0.f, a3 = 0.f;
        #pragma unroll 2
        for (int k = part; k < total; k += 8) {
            float wv = wl[k];
            float4 h = *(const float4*)&g_hc[(size_t)jl[k] * OUT_F + lane * 4];
            a0 += wv * h.x; a1 += wv * h.y; a2 += wv * h.z; a3 += wv * h.w;
        }
        pacc[part][lane * 4 + 0] = a0;
        pacc[part][lane * 4 + 1] = a1;
        pacc[part][lane * 4 + 2] = a2;
        pacc[part][lane * 4 + 3] = a3;
        __syncthreads();
        if (tid < OUT_F) {
            float s = 0.f;
            #pragma unroll
            for (int p = 0; p < 8; p++) s += pacc[p][tid];
            out[(size_t)row * OUT_F + tid] = s * inv;
        }
        return;
    }

    // slow path (degree > CAP)
    {
        int f = tid & (OUT_F - 1);
        int half = tid >> 7;
        float zloc = 0.f;
        w = word;
        while (w) {
            int bpos = __ffs(w) - 1; w &= w - 1;
            int j = (tid << 5) + bpos;
            float2 sd = g_sd[j];
            float a = ca * lrelu(sci + sd.x) + cs * lrelu(ssi + sd.y);
            zloc += __expf(a - m);
        }
        float Z = blockReduceSum(zloc, red);
        float inv = 1.f / Z;
        float acc = 0.f;
        for (int c = 0; c < NWORDS / 32; c++) {
            __syncthreads();
            if (tid == 0) s_cnt = 0;
            __syncthreads();
            if (tid < 32) {
                unsigned wd = g_adj[row * NWORDS + c * 32 + tid];
                int oo = atomicAdd(&s_cnt, __popc(wd));
                while (wd) {
                    int bpos = __ffs(wd) - 1; wd &= wd - 1;
                    int j = ((c * 32 + tid) << 5) + bpos;
                    float2 sd = g_sd[j];
                    float a = ca * lrelu(sci + sd.x) + cs * lrelu(ssi + sd.y);
                    wl[oo] = __expf(a - m);
                    jl[oo] = (unsigned short)j;
                    oo++;
                }
            }
            __syncthreads();
            int cc = s_cnt;
            for (int k = half; k < cc; k += 2)
                acc += wl[k] * g_hc[(size_t)jl[k] * OUT_F + f];
        }
        pacc[half][f] = acc;
        __syncthreads();
        if (tid < OUT_F)
            out[(size_t)row * OUT_F + tid] = (pacc[0][tid] + pacc[1][tid]) * inv;
    }
}

// ---------------- launch ----------------
extern "C" void kernel_launch(void* const* d_in, const int* in_sizes, int n_in,
                              void* d_out, int out_size) {
    const float* h_context   = (const float*)d_in[0];
    const float* h_structure = (const float*)d_in[1];
    const int*   edge        = (const int*)d_in[2];   // int32 or int64, detected on device
    const float* Wc_w        = (const float*)d_in[3];
    const float* Wc_b        = (const float*)d_in[4];
    const float* Ws_w        = (const float*)d_in[5];
    const float* Ws_b        = (const float*)d_in[6];
    const float* ac_w        = (const float*)d_in[7];
    const float* as_w        = (const float*)d_in[8];
    const float* Ws_coff     = (const float*)d_in[9];
    const float* Wc_coff     = (const float*)d_in[10];
    float* out = (float*)d_out;
    int E = in_sizes[2] / 2;

    k_init<<<(Nn * NWORDS / 4) / 256, 256>>>(edge, E);
    k_edges<<<(E + 255) / 256, 256>>>(edge, E, Ws_w, Ws_b, as_w, Ws_coff, Wc_coff);
    k_sscore<<<(Nn * 32) / 256, 256>>>(h_structure);
    k_gemm<<<Nn / BM, 256>>>(h_context, Wc_w, Wc_b, ac_w);
    k_attn<<<Nn, 256>>>(out, Ws_coff, Wc_coff);
}

// round 9
// speedup vs baseline: 1.3329x; 1.1385x over previous
#include <cuda_runtime.h>
#include <cuda_bf16.h>
#include <math.h>

#define Nn 8192
#define IN_F 256
#define OUT_F 128
#define NWORDS 256   // bitmap words per row (8192 bits)
#define CAP 2048     // fast-path neighbor list capacity (expected degree ~32)

// ---------------- device scratch (no allocs allowed) ----------------
// g_adj and g_vs start zeroed (static init) and are re-zeroed by k_attn
// after use, so every replay starts from a clean state with no init kernel.
__device__ float    g_hc[Nn * OUT_F];          // 4 MB
__device__ unsigned g_adj[Nn * NWORDS];        // 8 MB adjacency bitmap
__device__ float    g_sc_src[Nn];
__device__ float    g_ss_src[Nn];
__device__ float2   g_sd[Nn];                  // (sc_dst, ss_dst) packed
__device__ float    g_vs1[IN_F], g_vs2[IN_F];  // hs-GEMM fold vectors
__device__ float    g_scal[4];                 // ca, cs, bs1, bs2

__device__ __forceinline__ float lrelu(float x) { return x > 0.f ? x : 0.01f * x; }

// ---------------- reductions (start and end with __syncthreads) ----------------
__device__ float blockReduceMax(float v, float* red) {
    __syncthreads();
    #pragma unroll
    for (int o = 16; o; o >>= 1) v = fmaxf(v, __shfl_xor_sync(0xffffffffu, v, o));
    int w = threadIdx.x >> 5;
    if ((threadIdx.x & 31) == 0) red[w] = v;
    __syncthreads();
    if (threadIdx.x < 32) {
        float x = (threadIdx.x < (blockDim.x >> 5)) ? red[threadIdx.x] : -INFINITY;
        #pragma unroll
        for (int o = 4; o; o >>= 1) x = fmaxf(x, __shfl_xor_sync(0xffffffffu, x, o));
        if (threadIdx.x == 0) red[0] = x;
    }
    __syncthreads();
    return red[0];
}

__device__ float blockReduceSum(float v, float* red) {
    __syncthreads();
    #pragma unroll
    for (int o = 16; o; o >>= 1) v += __shfl_xor_sync(0xffffffffu, v, o);
    int w = threadIdx.x >> 5;
    if ((threadIdx.x & 31) == 0) red[w] = v;
    __syncthreads();
    if (threadIdx.x < 32) {
        float x = (threadIdx.x < (blockDim.x >> 5)) ? red[threadIdx.x] : 0.f;
        #pragma unroll
        for (int o = 4; o; o >>= 1) x += __shfl_xor_sync(0xffffffffu, x, o);
        if (threadIdx.x == 0) red[0] = x;
    }
    __syncthreads();
    return red[0];
}

// ---------------- kernels ----------------
// Edge bitmap build with block-local int32/int64 detection; blocks 0..7 also
// accumulate the hs-GEMM fold into g_vs (atomicAdd; g_vs zeroed by prior
// k_attn / static init); block 8 does bias dots + coefficient abs.
__global__ void k_edges(const int* __restrict__ p32, int E,
                        const float* __restrict__ Ws_w,
                        const float* __restrict__ Ws_b,
                        const float* __restrict__ as_w,
                        const float* __restrict__ Ws_coff,
                        const float* __restrict__ Wc_coff) {
    int tid = threadIdx.x;
    int e = blockIdx.x * blockDim.x + tid;
    // int64 little-endian with ids < 8192 -> every odd 32-bit word is 0.
    int hiw = 0;
    if (e < E) hiw = (p32[2 * e + 1] != 0);
    int isi32 = __syncthreads_or(hiw);
    if (e < E) {
        int r, c;
        if (isi32) {
            r = p32[e];
            c = p32[E + e];
        } else {
            const long long* p64 = (const long long*)p32;
            r = (int)p64[e];
            c = (int)p64[E + e];
        }
        if ((unsigned)r < Nn && (unsigned)c < Nn)
            atomicOr(&g_adj[r * NWORDS + (c >> 5)], 1u << (c & 31));
    }
    if (blockIdx.x < 8) {
        float v1 = 0.f, v2 = 0.f;
        #pragma unroll
        for (int i = 0; i < 16; i++) {
            int f = blockIdx.x * 16 + i;
            float w = Ws_w[f * IN_F + tid];
            v1 += w * as_w[f];
            v2 += w * as_w[OUT_F + f];
        }
        atomicAdd(&g_vs1[tid], v1);
        atomicAdd(&g_vs2[tid], v2);
    } else if (blockIdx.x == 8 && tid < 32) {
        float b1 = 0.f, b2 = 0.f;
        #pragma unroll
        for (int i = 0; i < 4; i++) {
            int f = tid + 32 * i;
            float wb = Ws_b[f];
            b1 += wb * as_w[f];
            b2 += wb * as_w[OUT_F + f];
        }
        #pragma unroll
        for (int o = 16; o; o >>= 1) {
            b1 += __shfl_xor_sync(0xffffffffu, b1, o);
            b2 += __shfl_xor_sync(0xffffffffu, b2, o);
        }
        if (tid == 0) {
            g_scal[0] = fabsf(Ws_coff[0]);  // multiplies alpha_c
            g_scal[1] = fabsf(Wc_coff[0]);  // multiplies alpha_s
            g_scal[2] = b1;
            g_scal[3] = b2;
        }
    }
}

// ---------------- split-bf16 tensor-core GEMM + fused structure scores -----
// hc = h_context @ Wc_w^T + Wc_b via mma.sync m16n8k16 bf16:
//   a*b ~= a_hi*b_hi + a_hi*b_lo + a_lo*b_hi   (fp32 accumulate)
// Each block also computes the structure scores for its own 64 rows first.
#define BM 64
#define BK 32
#define KCHUNKS (IN_F / BK)
#define APAD 40   // bf16 elems per row in smem (32 + 8 pad)

__device__ __forceinline__ void mma_bf16(float* c, const unsigned* a,
                                         unsigned b0, unsigned b1) {
    asm volatile(
        "mma.sync.aligned.m16n8k16.row.col.f32.bf16.bf16.f32 "
        "{%0,%1,%2,%3}, {%4,%5,%6,%7}, {%8,%9}, {%0,%1,%2,%3};"
        : "+f"(c[0]), "+f"(c[1]), "+f"(c[2]), "+f"(c[3])
        : "r"(a[0]), "r"(a[1]), "r"(a[2]), "r"(a[3]), "r"(b0), "r"(b1));
}

// pack two floats to bf16x2: low half = x, high half = y
__device__ __forceinline__ unsigned pk2(float x, float y) {
    unsigned r;
    asm("cvt.rn.bf16x2.f32 %0, %1, %2;" : "=r"(r) : "f"(y), "f"(x));
    return r;
}
__device__ __forceinline__ float bflo(unsigned u) { return __uint_as_float(u << 16); }
__device__ __forceinline__ float bfhi(unsigned u) { return __uint_as_float(u & 0xffff0000u); }

// convert float4 -> bf16 hi/lo planes, 8-byte stores
__device__ __forceinline__ void conv_sts(float4 v, __nv_bfloat16* hip, __nv_bfloat16* lop) {
    unsigned h0 = pk2(v.x, v.y);
    unsigned h1 = pk2(v.z, v.w);
    unsigned l0 = pk2(v.x - bflo(h0), v.y - bfhi(h0));
    unsigned l1 = pk2(v.z - bflo(h1), v.w - bfhi(h1));
    *(uint2*)hip = make_uint2(h0, h1);
    *(uint2*)lop = make_uint2(l0, l1);
}

__global__ void __launch_bounds__(256) k_gemm(const float* __restrict__ A,
                                              const float* __restrict__ W,
                                              const float* __restrict__ b,
                                              const float* __restrict__ ac_w,
                                              const float* __restrict__ hstruct) {
    __shared__ __align__(16) __nv_bfloat16 A_s[2][BM][APAD];      // 10.2 KB
    __shared__ __align__(16) __nv_bfloat16 W_s[2][OUT_F][APAD];   // 20.5 KB
    __shared__ float p_s1[8][16], p_s2[8][16];

    int tid = threadIdx.x;
    int lane = tid & 31;
    int warp = tid >> 5;
    int block_m = blockIdx.x * BM;

    // ---- fused structure scores for this block's 64 rows (warp = 8 rows) ----
    {
        float w1[8], w2[8];
        #pragma unroll
        for (int e = 0; e < 8; e++) {
            w1[e] = g_vs1[lane + 32 * e];
            w2[e] = g_vs2[lane + 32 * e];
        }
        float bs1 = g_scal[2], bs2 = g_scal[3];
        #pragma unroll
        for (int r = 0; r < 8; r++) {
            int row = block_m + warp * 8 + r;
            const float* x = hstruct + (size_t)row * IN_F;
            float v[8];
            float m = -INFINITY;
            #pragma unroll
            for (int e = 0; e < 8; e++) { v[e] = x[lane + 32 * e]; m = fmaxf(m, v[e]); }
            #pragma unroll
            for (int o = 16; o; o >>= 1) m = fmaxf(m, __shfl_xor_sync(0xffffffffu, m, o));
            float z = 0.f, d1 = 0.f, d2 = 0.f;
            #pragma unroll
            for (int e = 0; e < 8; e++) {
                float ex = __expf(v[e] - m);
                z  += ex;
                d1 += ex * w1[e];
                d2 += ex * w2[e];
            }
            #pragma unroll
            for (int o = 16; o; o >>= 1) {
                z  += __shfl_xor_sync(0xffffffffu, z,  o);
                d1 += __shfl_xor_sync(0xffffffffu, d1, o);
                d2 += __shfl_xor_sync(0xffffffffu, d2, o);
            }
            if (lane == 0) {
                g_ss_src[row] = d1 / z + bs1;
                g_sd[row].y   = d2 / z + bs2;
            }
        }
    }

    // ---- tensor-core mainloop ----
    int mrow = (warp >> 1) * 16;     // 0,16,32,48
    int nbase = (warp & 1) * 64;     // 0 or 64
    int g  = lane >> 2;              // 0..7
    int t4 = lane & 3;               // 0..3
    int arow = tid >> 3;             // 0..31
    int akc  = (tid & 7) * 4;        // 0,4,..28 within chunk
    float acc[8][4] = {};

    float4 ra0, ra1, rw0, rw1, rw2, rw3;
    #define GLD(c0_)                                                          \
        ra0 = *(const float4*)&A[(size_t)(block_m + arow) * IN_F + (c0_) + akc];      \
        ra1 = *(const float4*)&A[(size_t)(block_m + arow + 32) * IN_F + (c0_) + akc]; \
        rw0 = *(const float4*)&W[(size_t)arow * IN_F + (c0_) + akc];                  \
        rw1 = *(const float4*)&W[(size_t)(arow + 32) * IN_F + (c0_) + akc];           \
        rw2 = *(const float4*)&W[(size_t)(arow + 64) * IN_F + (c0_) + akc];           \
        rw3 = *(const float4*)&W[(size_t)(arow + 96) * IN_F + (c0_) + akc];

    GLD(0);

    #pragma unroll 1
    for (int c = 0; c < KCHUNKS; c++) {
        conv_sts(ra0, &A_s[0][arow][akc],      &A_s[1][arow][akc]);
        conv_sts(ra1, &A_s[0][arow + 32][akc], &A_s[1][arow + 32][akc]);
        conv_sts(rw0, &W_s[0][arow][akc],      &W_s[1][arow][akc]);
        conv_sts(rw1, &W_s[0][arow + 32][akc], &W_s[1][arow + 32][akc]);
        conv_sts(rw2, &W_s[0][arow + 64][akc], &W_s[1][arow + 64][akc]);
        conv_sts(rw3, &W_s[0][arow + 96][akc], &W_s[1][arow + 96][akc]);
        __syncthreads();
        if (c < KCHUNKS - 1) { GLD((c + 1) * BK); }

        #pragma unroll
        for (int ks = 0; ks < 2; ks++) {
            int kb = ks * 16 + 2 * t4;
            unsigned ah[4], al[4];
            ah[0] = *(const unsigned*)&A_s[0][mrow + g][kb];
            ah[1] = *(const unsigned*)&A_s[0][mrow + g + 8][kb];
            ah[2] = *(const unsigned*)&A_s[0][mrow + g][kb + 8];
            ah[3] = *(const unsigned*)&A_s[0][mrow + g + 8][kb + 8];
            al[0] = *(const unsigned*)&A_s[1][mrow + g][kb];
            al[1] = *(const unsigned*)&A_s[1][mrow + g + 8][kb];
            al[2] = *(const unsigned*)&A_s[1][mrow + g][kb + 8];
            al[3] = *(const unsigned*)&A_s[1][mrow + g + 8][kb + 8];
            #pragma unroll
            for (int t = 0; t < 8; t++) {
                int n = nbase + 8 * t + g;
                unsigned bh0 = *(const unsigned*)&W_s[0][n][kb];
                unsigned bh1 = *(const unsigned*)&W_s[0][n][kb + 8];
                unsigned bl0 = *(const unsigned*)&W_s[1][n][kb];
                unsigned bl1 = *(const unsigned*)&W_s[1][n][kb + 8];
                mma_bf16(acc[t], ah, bh0, bh1);
                mma_bf16(acc[t], ah, bl0, bl1);
                mma_bf16(acc[t], al, bh0, bh1);
            }
        }
        __syncthreads();
    }

    // epilogue: bias add, hc store, fused context scores
    float s1g = 0.f, s1h = 0.f, s2g = 0.f, s2h = 0.f;
    int row0 = block_m + mrow + g;
    #pragma unroll
    for (int t = 0; t < 8; t++) {
        int col = nbase + 8 * t + 2 * t4;
        float2 bb  = *(const float2*)&b[col];
        float2 w1v = *(const float2*)&ac_w[col];
        float2 w2v = *(const float2*)&ac_w[OUT_F + col];
        float c0 = acc[t][0] + bb.x;
        float c1 = acc[t][1] + bb.y;
        float c2 = acc[t][2] + bb.x;
        float c3 = acc[t][3] + bb.y;
        *(float2*)&g_hc[(size_t)row0 * OUT_F + col]       = make_float2(c0, c1);
        *(float2*)&g_hc[(size_t)(row0 + 8) * OUT_F + col] = make_float2(c2, c3);
        s1g += c0 * w1v.x + c1 * w1v.y;
        s1h += c2 * w1v.x + c3 * w1v.y;
        s2g += c0 * w2v.x + c1 * w2v.y;
        s2h += c2 * w2v.x + c3 * w2v.y;
    }
    #pragma unroll
    for (int o = 1; o <= 2; o <<= 1) {
        s1g += __shfl_xor_sync(0xffffffffu, s1g, o);
        s1h += __shfl_xor_sync(0xffffffffu, s1h, o);
        s2g += __shfl_xor_sync(0xffffffffu, s2g, o);
        s2h += __shfl_xor_sync(0xffffffffu, s2h, o);
    }
    if (t4 == 0) {
        p_s1[warp][g] = s1g;  p_s1[warp][g + 8] = s1h;
        p_s2[warp][g] = s2g;  p_s2[warp][g + 8] = s2h;
    }
    __syncthreads();
    if (tid < BM) {
        int mt = tid >> 4, r = tid & 15;
        int row = block_m + mt * 16 + r;
        g_sc_src[row] = p_s1[2 * mt][r] + p_s1[2 * mt + 1][r];
        g_sd[row].x   = p_s2[2 * mt][r] + p_s2[2 * mt + 1][r];
    }
}

// Per-row sparse masked softmax + weighted hc gather.
// Also re-zeroes its bitmap row (after last read) and block 0 re-zeroes g_vs,
// so the next replay starts from clean state without an init kernel.
__global__ void __launch_bounds__(256) k_attn(float* __restrict__ out,
                                              const float* __restrict__ Ws_coff,
                                              const float* __restrict__ Wc_coff) {
    __shared__ float wl[CAP];
    __shared__ unsigned short jl[CAP];
    __shared__ float red[32];
    __shared__ int s_cnt;
    __shared__ float pacc[8][OUT_F];

    int row = blockIdx.x;
    int tid = threadIdx.x;
    int lane = tid & 31;
    int part = tid >> 5;    // 0..7
    float ca = fabsf(Ws_coff[0]);   // multiplies alpha_c (per reference)
    float cs = fabsf(Wc_coff[0]);   // multiplies alpha_s
    float sci = g_sc_src[row], ssi = g_ss_src[row];
    unsigned word = g_adj[row * NWORDS + tid];

    if (tid == 0) s_cnt = 0;
    if (row == 0) { g_vs1[tid] = 0.f; g_vs2[tid] = 0.f; }  // reset fold accumulators
    __syncthreads();

    int o = atomicAdd(&s_cnt, __popc(word));
    float m = -INFINITY;
    unsigned w = word;
    while (w) {
        int bpos = __ffs(w) - 1; w &= w - 1;
        int j = (tid << 5) + bpos;
        float2 sd = g_sd[j];
        float a = ca * lrelu(sci + sd.x) + cs * lrelu(ssi + sd.y);
        m = fmaxf(m, a);
        if (o < CAP) { wl[o] = a; jl[o] = (unsigned short)j; }
        o++;
    }
    m = blockReduceMax(m, red);
    int total = s_cnt;

    if (total == 0) {
        if (part == 0 || part == 1) {
            int f = tid & (OUT_F - 1);
            float acc = 0.f;
            for (int j = (tid >> 7); j < Nn; j += 2) acc += g_hc[(size_t)j * OUT_F + f];
            pacc[tid >> 7][f] = acc;
        }
        __syncthreads();
        if (tid < OUT_F)
            out[(size_t)row * OUT_F + tid] = (pacc[0][tid] + pacc[1][tid]) / (float)Nn;
        return;
    }

    if (total <= CAP) {
        if (word) g_adj[row * NWORDS + tid] = 0u;   // last read done; reset for next replay
        float zloc = 0.f;
        for (int k = tid; k < total; k += 256) {
            float e = __expf(wl[k] - m);
            wl[k] = e;
            zloc += e;
        }
        float Z = blockReduceSum(zloc, red);
        float inv = 1.f / Z;
        float a0 = 0.f, a1 = 0.f, a2 = 0.f, a3 = 0.f;
        #pragma unroll 2
        for (int k = part; k < total; k += 8) {
            float wv = wl[k];
            float4 h = *(const float4*)&g_hc[(size_t)jl[k] * OUT_F + lane * 4];
            a0 += wv * h.x; a1 += wv * h.y; a2 += wv * h.z; a3 += wv * h.w;
        }
        pacc[part][lane * 4 + 0] = a0;
        pacc[part][lane * 4 + 1] = a1;
        pacc[part][lane * 4 + 2] = a2;
        pacc[part][lane * 4 + 3] = a3;
        __syncthreads();
        if (tid < OUT_F) {
            float s = 0.f;
            #pragma unroll
            for (int p = 0; p < 8; p++) s += pacc[p][tid];
            out[(size_t)row * OUT_F + tid] = s * inv;
        }
        return;
    }

    // slow path (degree > CAP)
    {
        int f = tid & (OUT_F - 1);
        int half = tid >> 7;
        float zloc = 0.f;
        w = word;
        while (w) {
            int bpos = __ffs(w) - 1; w &= w - 1;
            int j = (tid << 5) + bpos;
            float2 sd = g_sd[j];
            float a = ca * lrelu(sci + sd.x) + cs * lrelu(ssi + sd.y);
            zloc += __expf(a - m);
        }
        float Z = blockReduceSum(zloc, red);
        float inv = 1.f / Z;
        float acc = 0.f;
        for (int c = 0; c < NWORDS / 32; c++) {
            __syncthreads();
            if (tid == 0) s_cnt = 0;
            __syncthreads();
            if (tid < 32) {
                unsigned wd = g_adj[row * NWORDS + c * 32 + tid];
                int oo = atomicAdd(&s_cnt, __popc(wd));
                while (wd) {
                    int bpos = __ffs(wd) - 1; wd &= wd - 1;
                    int j = ((c * 32 + tid) << 5) + bpos;
                    float2 sd = g_sd[j];
                    float a = ca * lrelu(sci + sd.x) + cs * lrelu(ssi + sd.y);
                    wl[oo] = __expf(a - m);
                    jl[oo] = (unsigned short)j;
                    oo++;
                }
            }
            __syncthreads();
            int cc = s_cnt;
            for (int k = half; k < cc; k += 2)
                acc += wl[k] * g_hc[(size_t)jl[k] * OUT_F + f];
        }
        if (word) g_adj[row * NWORDS + tid] = 0u;   // reset after final read
        pacc[half][f] = acc;
        __syncthreads();
        if (tid < OUT_F)
            out[(size_t)row * OUT_F + tid] = (pacc[0][tid] + pacc[1][tid]) * inv;
    }
}

// ---------------- launch ----------------
extern "C" void kernel_launch(void* const* d_in, const int* in_sizes, int n_in,
                              void* d_out, int out_size) {
    const float* h_context   = (const float*)d_in[0];
    const float* h_structure = (const float*)d_in[1];
    const int*   edge        = (const int*)d_in[2];   // int32 or int64, detected per block
    const float* Wc_w        = (const float*)d_in[3];
    const float* Wc_b        = (const float*)d_in[4];
    const float* Ws_w        = (const float*)d_in[5];
    const float* Ws_b        = (const float*)d_in[6];
    const float* ac_w        = (const float*)d_in[7];
    const float* as_w        = (const float*)d_in[8];
    const float* Ws_coff     = (const float*)d_in[9];
    const float* Wc_coff     = (const float*)d_in[10];
    float* out = (float*)d_out;
    int E = in_sizes[2] / 2;

    k_edges<<<(E + 255) / 256, 256>>>(edge, E, Ws_w, Ws_b, as_w, Ws_coff, Wc_coff);
    k_gemm<<<Nn / BM, 256>>>(h_context, Wc_w, Wc_b, ac_w, h_structure);
    k_attn<<<Nn, 256>>>(out, Ws_coff, Wc_coff);
}

// round 10
// speedup vs baseline: 1.4128x; 1.0600x over previous
#include <cuda_runtime.h>
#include <cuda_bf16.h>
#include <math.h>

#define Nn 8192
#define IN_F 256
#define OUT_F 128
#define NWORDS 256   // bitmap words per row (8192 bits)
#define CAP 2048     // fast-path neighbor list capacity (expected degree ~32)

// ---------------- device scratch (no allocs allowed) ----------------
// g_adj and g_vs start zeroed (static init) and are re-zeroed by k_attn
// after use, so every replay starts from a clean state with no init kernel.
__device__ float    g_hc[Nn * OUT_F];          // 4 MB
__device__ unsigned g_adj[Nn * NWORDS];        // 8 MB adjacency bitmap
__device__ float    g_sc_src[Nn];
__device__ float    g_ss_src[Nn];
__device__ float2   g_sd[Nn];                  // (sc_dst, ss_dst) packed
__device__ float    g_vs1[IN_F], g_vs2[IN_F];  // hs-GEMM fold vectors
__device__ float    g_scal[4];                 // ca, cs, bs1, bs2

__device__ __forceinline__ float lrelu(float x) { return x > 0.f ? x : 0.01f * x; }

// ---------------- reductions (start and end with __syncthreads) ----------------
__device__ float blockReduceMax(float v, float* red) {
    __syncthreads();
    #pragma unroll
    for (int o = 16; o; o >>= 1) v = fmaxf(v, __shfl_xor_sync(0xffffffffu, v, o));
    int w = threadIdx.x >> 5;
    if ((threadIdx.x & 31) == 0) red[w] = v;
    __syncthreads();
    if (threadIdx.x < 32) {
        float x = (threadIdx.x < (blockDim.x >> 5)) ? red[threadIdx.x] : -INFINITY;
        #pragma unroll
        for (int o = 4; o; o >>= 1) x = fmaxf(x, __shfl_xor_sync(0xffffffffu, x, o));
        if (threadIdx.x == 0) red[0] = x;
    }
    __syncthreads();
    return red[0];
}

__device__ float blockReduceSum(float v, float* red) {
    __syncthreads();
    #pragma unroll
    for (int o = 16; o; o >>= 1) v += __shfl_xor_sync(0xffffffffu, v, o);
    int w = threadIdx.x >> 5;
    if ((threadIdx.x & 31) == 0) red[w] = v;
    __syncthreads();
    if (threadIdx.x < 32) {
        float x = (threadIdx.x < (blockDim.x >> 5)) ? red[threadIdx.x] : 0.f;
        #pragma unroll
        for (int o = 4; o; o >>= 1) x += __shfl_xor_sync(0xffffffffu, x, o);
        if (threadIdx.x == 0) red[0] = x;
    }
    __syncthreads();
    return red[0];
}

// ---------------- kernels ----------------
// Edge bitmap build, 4 edges/thread vectorized, block-local i32/i64 detect;
// blocks 0..7 also accumulate the hs-GEMM fold into g_vs; block 8 does bias
// dots + coefficient abs.
__global__ void k_edges(const int* __restrict__ p32, int E,
                        const float* __restrict__ Ws_w,
                        const float* __restrict__ Ws_b,
                        const float* __restrict__ as_w,
                        const float* __restrict__ Ws_coff,
                        const float* __restrict__ Wc_coff) {
    int tid = threadIdx.x;
    int gid = blockIdx.x * blockDim.x + tid;
    int e0 = gid * 4;

    // detect: int64 little-endian ids < 8192 -> odd 32-bit words are all 0
    int hiw = 0;
    if (e0 + 3 < E) {
        int4 p0 = *(const int4*)&p32[2 * e0];
        int4 p1 = *(const int4*)&p32[2 * e0 + 4];
        hiw = ((p0.y | p0.w | p1.y | p1.w) != 0);
    } else {
        for (int i = e0; i < E; i++) hiw |= (p32[2 * i + 1] != 0);
    }
    int isi32 = __syncthreads_or(hiw);

    if (e0 < E) {
        int r[4], c[4];
        int n = (E - e0 >= 4) ? 4 : (E - e0);
        if (!isi32) {
            if (n == 4) {
                int4 p0 = *(const int4*)&p32[2 * e0];
                int4 p1 = *(const int4*)&p32[2 * e0 + 4];
                int4 q0 = *(const int4*)&p32[2 * (E + e0)];
                int4 q1 = *(const int4*)&p32[2 * (E + e0) + 4];
                r[0] = p0.x; r[1] = p0.z; r[2] = p1.x; r[3] = p1.z;
                c[0] = q0.x; c[1] = q0.z; c[2] = q1.x; c[3] = q1.z;
            } else {
                const long long* p64 = (const long long*)p32;
                for (int i = 0; i < n; i++) {
                    r[i] = (int)p64[e0 + i];
                    c[i] = (int)p64[E + e0 + i];
                }
            }
        } else {
            if (n == 4 && ((E & 3) == 0)) {
                int4 rv = *(const int4*)&p32[e0];
                int4 cv = *(const int4*)&p32[E + e0];
                r[0] = rv.x; r[1] = rv.y; r[2] = rv.z; r[3] = rv.w;
                c[0] = cv.x; c[1] = cv.y; c[2] = cv.z; c[3] = cv.w;
            } else {
                for (int i = 0; i < n; i++) {
                    r[i] = p32[e0 + i];
                    c[i] = p32[E + e0 + i];
                }
            }
        }
        #pragma unroll
        for (int i = 0; i < 4; i++) {
            if (i < n && (unsigned)r[i] < Nn && (unsigned)c[i] < Nn)
                atomicOr(&g_adj[r[i] * NWORDS + (c[i] >> 5)], 1u << (c[i] & 31));
        }
    }

    if (blockIdx.x < 8) {
        float v1 = 0.f, v2 = 0.f;
        #pragma unroll
        for (int i = 0; i < 16; i++) {
            int f = blockIdx.x * 16 + i;
            float w = Ws_w[f * IN_F + tid];
            v1 += w * as_w[f];
            v2 += w * as_w[OUT_F + f];
        }
        atomicAdd(&g_vs1[tid], v1);
        atomicAdd(&g_vs2[tid], v2);
    } else if (blockIdx.x == 8 && tid < 32) {
        float b1 = 0.f, b2 = 0.f;
        #pragma unroll
        for (int i = 0; i < 4; i++) {
            int f = tid + 32 * i;
            float wb = Ws_b[f];
            b1 += wb * as_w[f];
            b2 += wb * as_w[OUT_F + f];
        }
        #pragma unroll
        for (int o = 16; o; o >>= 1) {
            b1 += __shfl_xor_sync(0xffffffffu, b1, o);
            b2 += __shfl_xor_sync(0xffffffffu, b2, o);
        }
        if (tid == 0) {
            g_scal[0] = fabsf(Ws_coff[0]);  // multiplies alpha_c
            g_scal[1] = fabsf(Wc_coff[0]);  // multiplies alpha_s
            g_scal[2] = b1;
            g_scal[3] = b2;
        }
    }
}

// ---------------- split-bf16 tensor-core GEMM + fused structure scores -----
// hc = h_context @ Wc_w^T + Wc_b via mma.sync m16n8k16 bf16:
//   a*b ~= a_hi*b_hi + a_hi*b_lo + a_lo*b_hi   (fp32 accumulate)
// BM=32 (grid 256, 2 blocks/SM), double-buffered staging, one sync/chunk.
#define BM 32
#define BK 32
#define KCHUNKS (IN_F / BK)
#define APAD 40   // bf16 elems per row in smem (32 + 8 pad)

__device__ __forceinline__ void mma_bf16(float* c, const unsigned* a,
                                         unsigned b0, unsigned b1) {
    asm volatile(
        "mma.sync.aligned.m16n8k16.row.col.f32.bf16.bf16.f32 "
        "{%0,%1,%2,%3}, {%4,%5,%6,%7}, {%8,%9}, {%0,%1,%2,%3};"
        : "+f"(c[0]), "+f"(c[1]), "+f"(c[2]), "+f"(c[3])
        : "r"(a[0]), "r"(a[1]), "r"(a[2]), "r"(a[3]), "r"(b0), "r"(b1));
}

// pack two floats to bf16x2: low half = x, high half = y
__device__ __forceinline__ unsigned pk2(float x, float y) {
    unsigned r;
    asm("cvt.rn.bf16x2.f32 %0, %1, %2;" : "=r"(r) : "f"(y), "f"(x));
    return r;
}
__device__ __forceinline__ float bflo(unsigned u) { return __uint_as_float(u << 16); }
__device__ __forceinline__ float bfhi(unsigned u) { return __uint_as_float(u & 0xffff0000u); }

// convert float4 -> bf16 hi/lo planes, 8-byte stores
__device__ __forceinline__ void conv_sts(float4 v, __nv_bfloat16* hip, __nv_bfloat16* lop) {
    unsigned h0 = pk2(v.x, v.y);
    unsigned h1 = pk2(v.z, v.w);
    unsigned l0 = pk2(v.x - bflo(h0), v.y - bfhi(h0));
    unsigned l1 = pk2(v.z - bflo(h1), v.w - bfhi(h1));
    *(uint2*)hip = make_uint2(h0, h1);
    *(uint2*)lop = make_uint2(l0, l1);
}

__global__ void __launch_bounds__(256, 2) k_gemm(const float* __restrict__ A,
                                                 const float* __restrict__ W,
                                                 const float* __restrict__ b,
                                                 const float* __restrict__ ac_w,
                                                 const float* __restrict__ hstruct) {
    __shared__ __align__(16) __nv_bfloat16 A_s[2][2][BM][APAD];      // 10.2 KB
    __shared__ __align__(16) __nv_bfloat16 W_s[2][2][OUT_F][APAD];   // 41 KB
    __shared__ float p_s1[8][16], p_s2[8][16];

    int tid = threadIdx.x;
    int lane = tid & 31;
    int warp = tid >> 5;
    int block_m = blockIdx.x * BM;

    // ---- fused structure scores for this block's 32 rows (warp = 4 rows) ----
    {
        float w1[8], w2[8];
        #pragma unroll
        for (int e = 0; e < 8; e++) {
            w1[e] = g_vs1[lane + 32 * e];
            w2[e] = g_vs2[lane + 32 * e];
        }
        float bs1 = g_scal[2], bs2 = g_scal[3];
        #pragma unroll
        for (int r = 0; r < 4; r++) {
            int row = block_m + warp * 4 + r;
            const float* x = hstruct + (size_t)row * IN_F;
            float v[8];
            float m = -INFINITY;
            #pragma unroll
            for (int e = 0; e < 8; e++) { v[e] = x[lane + 32 * e]; m = fmaxf(m, v[e]); }
            #pragma unroll
            for (int o = 16; o; o >>= 1) m = fmaxf(m, __shfl_xor_sync(0xffffffffu, m, o));
            float z = 0.f, d1 = 0.f, d2 = 0.f;
            #pragma unroll
            for (int e = 0; e < 8; e++) {
                float ex = __expf(v[e] - m);
                z  += ex;
                d1 += ex * w1[e];
                d2 += ex * w2[e];
            }
            #pragma unroll
            for (int o = 16; o; o >>= 1) {
                z  += __shfl_xor_sync(0xffffffffu, z,  o);
                d1 += __shfl_xor_sync(0xffffffffu, d1, o);
                d2 += __shfl_xor_sync(0xffffffffu, d2, o);
            }
            if (lane == 0) {
                g_ss_src[row] = d1 / z + bs1;
                g_sd[row].y   = d2 / z + bs2;
            }
        }
    }

    // ---- tensor-core mainloop ----
    int mrow = (warp >> 2) * 16;     // 0 or 16
    int nbase = (warp & 3) * 32;     // 0,32,64,96
    int g  = lane >> 2;              // 0..7
    int t4 = lane & 3;               // 0..3
    int arow = tid >> 3;             // 0..31
    int akc  = (tid & 7) * 4;        // 0,4,..28 within chunk
    float acc[4][4] = {};

    float4 ra0, rw0, rw1, rw2, rw3;
    #define GLD(c0_)                                                          \
        ra0 = *(const float4*)&A[(size_t)(block_m + arow) * IN_F + (c0_) + akc];      \
        rw0 = *(const float4*)&W[(size_t)arow * IN_F + (c0_) + akc];                  \
        rw1 = *(const float4*)&W[(size_t)(arow + 32) * IN_F + (c0_) + akc];           \
        rw2 = *(const float4*)&W[(size_t)(arow + 64) * IN_F + (c0_) + akc];           \
        rw3 = *(const float4*)&W[(size_t)(arow + 96) * IN_F + (c0_) + akc];

    #define CONV(buf_)                                                        \
        conv_sts(ra0, &A_s[buf_][0][arow][akc],      &A_s[buf_][1][arow][akc]);      \
        conv_sts(rw0, &W_s[buf_][0][arow][akc],      &W_s[buf_][1][arow][akc]);      \
        conv_sts(rw1, &W_s[buf_][0][arow + 32][akc], &W_s[buf_][1][arow + 32][akc]); \
        conv_sts(rw2, &W_s[buf_][0][arow + 64][akc], &W_s[buf_][1][arow + 64][akc]); \
        conv_sts(rw3, &W_s[buf_][0][arow + 96][akc], &W_s[buf_][1][arow + 96][akc]);

    GLD(0);
    CONV(0);
    __syncthreads();

    #pragma unroll 1
    for (int c = 0; c < KCHUNKS; c++) {
        int buf = c & 1;
        if (c < KCHUNKS - 1) { GLD((c + 1) * BK); }
        #pragma unroll
        for (int ks = 0; ks < 2; ks++) {
            int kb = ks * 16 + 2 * t4;
            unsigned ah[4], al[4];
            ah[0] = *(const unsigned*)&A_s[buf][0][mrow + g][kb];
            ah[1] = *(const unsigned*)&A_s[buf][0][mrow + g + 8][kb];
            ah[2] = *(const unsigned*)&A_s[buf][0][mrow + g][kb + 8];
            ah[3] = *(const unsigned*)&A_s[buf][0][mrow + g + 8][kb + 8];
            al[0] = *(const unsigned*)&A_s[buf][1][mrow + g][kb];
            al[1] = *(const unsigned*)&A_s[buf][1][mrow + g + 8][kb];
            al[2] = *(const unsigned*)&A_s[buf][1][mrow + g][kb + 8];
            al[3] = *(const unsigned*)&A_s[buf][1][mrow + g + 8][kb + 8];
            #pragma unroll
            for (int t = 0; t < 4; t++) {
                int n = nbase + 8 * t + g;
                unsigned bh0 = *(const unsigned*)&W_s[buf][0][n][kb];
                unsigned bh1 = *(const unsigned*)&W_s[buf][0][n][kb + 8];
                unsigned bl0 = *(const unsigned*)&W_s[buf][1][n][kb];
                unsigned bl1 = *(const unsigned*)&W_s[buf][1][n][kb + 8];
                mma_bf16(acc[t], ah, bh0, bh1);
                mma_bf16(acc[t], ah, bl0, bl1);
                mma_bf16(acc[t], al, bh0, bh1);
            }
        }
        if (c < KCHUNKS - 1) {
            CONV(buf ^ 1);
            __syncthreads();
        }
    }

    // epilogue: bias add, hc store, fused context scores
    float s1g = 0.f, s1h = 0.f, s2g = 0.f, s2h = 0.f;
    int row0 = block_m + mrow + g;
    #pragma unroll
    for (int t = 0; t < 4; t++) {
        int col = nbase + 8 * t + 2 * t4;
        float2 bb  = *(const float2*)&b[col];
        float2 w1v = *(const float2*)&ac_w[col];
        float2 w2v = *(const float2*)&ac_w[OUT_F + col];
        float c0 = acc[t][0] + bb.x;
        float c1 = acc[t][1] + bb.y;
        float c2 = acc[t][2] + bb.x;
        float c3 = acc[t][3] + bb.y;
        *(float2*)&g_hc[(size_t)row0 * OUT_F + col]       = make_float2(c0, c1);
        *(float2*)&g_hc[(size_t)(row0 + 8) * OUT_F + col] = make_float2(c2, c3);
        s1g += c0 * w1v.x + c1 * w1v.y;
        s1h += c2 * w1v.x + c3 * w1v.y;
        s2g += c0 * w2v.x + c1 * w2v.y;
        s2h += c2 * w2v.x + c3 * w2v.y;
    }
    #pragma unroll
    for (int o = 1; o <= 2; o <<= 1) {
        s1g += __shfl_xor_sync(0xffffffffu, s1g, o);
        s1h += __shfl_xor_sync(0xffffffffu, s1h, o);
        s2g += __shfl_xor_sync(0xffffffffu, s2g, o);
        s2h += __shfl_xor_sync(0xffffffffu, s2h, o);
    }
    if (t4 == 0) {
        p_s1[warp][g] = s1g;  p_s1[warp][g + 8] = s1h;
        p_s2[warp][g] = s2g;  p_s2[warp][g + 8] = s2h;
    }
    __syncthreads();
    if (tid < BM) {
        int mt = tid >> 4, r = tid & 15;
        int row = block_m + mt * 16 + r;
        float s1 = 0.f, s2 = 0.f;
        #pragma unroll
        for (int w = 0; w < 4; w++) {
            s1 += p_s1[mt * 4 + w][r];
            s2 += p_s2[mt * 4 + w][r];
        }
        g_sc_src[row] = s1;
        g_sd[row].x   = s2;
    }
}

// Per-row sparse masked softmax + weighted hc gather.
// Also re-zeroes its bitmap row (after last read) and block 0 re-zeroes g_vs.
__global__ void __launch_bounds__(256) k_attn(float* __restrict__ out,
                                              const float* __restrict__ Ws_coff,
                                              const float* __restrict__ Wc_coff) {
    __shared__ float wl[CAP];
    __shared__ unsigned short jl[CAP];
    __shared__ float red[32];
    __shared__ int s_cnt;
    __shared__ float pacc[8][OUT_F];

    int row = blockIdx.x;
    int tid = threadIdx.x;
    int lane = tid & 31;
    int part = tid >> 5;    // 0..7
    float ca = fabsf(Ws_coff[0]);   // multiplies alpha_c (per reference)
    float cs = fabsf(Wc_coff[0]);   // multiplies alpha_s
    float sci = g_sc_src[row], ssi = g_ss_src[row];
    unsigned word = g_adj[row * NWORDS + tid];

    if (tid == 0) s_cnt = 0;
    if (row == 0) { g_vs1[tid] = 0.f; g_vs2[tid] = 0.f; }  // reset fold accumulators
    __syncthreads();

    int o = atomicAdd(&s_cnt, __popc(word));
    float m = -INFINITY;
    unsigned w = word;
    while (w) {
        int bpos = __ffs(w) - 1; w &= w - 1;
        int j = (tid << 5) + bpos;
        float2 sd = g_sd[j];
        float a = ca * lrelu(sci + sd.x) + cs * lrelu(ssi + sd.y);
        m = fmaxf(m, a);
        if (o < CAP) { wl[o] = a; jl[o] = (unsigned short)j; }
        o++;
    }
    m = blockReduceMax(m, red);
    int total = s_cnt;

    if (total == 0) {
        if (part == 0 || part == 1) {
            int f = tid & (OUT_F - 1);
            float acc = 0.f;
            for (int j = (tid >> 7); j < Nn; j += 2) acc += g_hc[(size_t)j * OUT_F + f];
            pacc[tid >> 7][f] = acc;
        }
        __syncthreads();
        if (tid < OUT_F)
            out[(size_t)row * OUT_F + tid] = (pacc[0][tid] + pacc[1][tid]) / (float)Nn;
        return;
    }

    if (total <= CAP) {
        if (word) g_adj[row * NWORDS + tid] = 0u;   // last read done; reset for next replay
        float zloc = 0.f;
        for (int k = tid; k < total; k += 256) {
            float e = __expf(wl[k] - m);
            wl[k] = e;
            zloc += e;
        }
        float Z = blockReduceSum(zloc, red);
        float inv = 1.f / Z;
        float a0 = 0.f, a1 = 0.f, a2 = 0.f, a3 = 0.f;
        #pragma unroll 2
        for (int k = part; k < total; k += 8) {
            float wv = wl[k];
            float4 h = *(const float4*)&g_hc[(size_t)jl[k] * OUT_F + lane * 4];
            a0 += wv * h.x; a1 += wv * h.y; a2 += wv * h.z; a3 += wv * h.w;
        }
        pacc[part][lane * 4 + 0] = a0;
        pacc[part][lane * 4 + 1] = a1;
        pacc[part][lane * 4 + 2] = a2;
        pacc[part][lane * 4 + 3] = a3;
        __syncthreads();
        if (tid < OUT_F) {
            float s = 0.f;
            #pragma unroll
            for (int p = 0; p < 8; p++) s += pacc[p][tid];
            out[(size_t)row * OUT_F + tid] = s * inv;
        }
        return;
    }

    // slow path (degree > CAP)
    {
        int f = tid & (OUT_F - 1);
        int half = tid >> 7;
        float zloc = 0.f;
        w = word;
        while (w) {
            int bpos = __ffs(w) - 1; w &= w - 1;
            int j = (tid << 5) + bpos;
            float2 sd = g_sd[j];
            float a = ca * lrelu(sci + sd.x) + cs * lrelu(ssi + sd.y);
            zloc += __expf(a - m);
        }
        float Z = blockReduceSum(zloc, red);
        float inv = 1.f / Z;
        float acc = 0.f;
        for (int c = 0; c < NWORDS / 32; c++) {
            __syncthreads();
            if (tid == 0) s_cnt = 0;
            __syncthreads();
            if (tid < 32) {
                unsigned wd = g_adj[row * NWORDS + c * 32 + tid];
                int oo = atomicAdd(&s_cnt, __popc(wd));
                while (wd) {
                    int bpos = __ffs(wd) - 1; wd &= wd - 1;
                    int j = ((c * 32 + tid) << 5) + bpos;
                    float2 sd = g_sd[j];
                    float a = ca * lrelu(sci + sd.x) + cs * lrelu(ssi + sd.y);
                    wl[oo] = __expf(a - m);
                    jl[oo] = (unsigned short)j;
                    oo++;
                }
            }
            __syncthreads();
            int cc = s_cnt;
            for (int k = half; k < cc; k += 2)
                acc += wl[k] * g_hc[(size_t)jl[k] * OUT_F + f];
        }
        if (word) g_adj[row * NWORDS + tid] = 0u;   // reset after final read
        pacc[half][f] = acc;
        __syncthreads();
        if (tid < OUT_F)
            out[(size_t)row * OUT_F + tid] = (pacc[0][tid] + pacc[1][tid]) * inv;
    }
}

// ---------------- launch ----------------
extern "C" void kernel_launch(void* const* d_in, const int* in_sizes, int n_in,
                              void* d_out, int out_size) {
    const float* h_context   = (const float*)d_in[0];
    const float* h_structure = (const float*)d_in[1];
    const int*   edge        = (const int*)d_in[2];   // int32 or int64, detected per block
    const float* Wc_w        = (const float*)d_in[3];
    const float* Wc_b        = (const float*)d_in[4];
    const float* Ws_w        = (const float*)d_in[5];
    const float* Ws_b        = (const float*)d_in[6];
    const float* ac_w        = (const float*)d_in[7];
    const float* as_w        = (const float*)d_in[8];
    const float* Ws_coff     = (const float*)d_in[9];
    const float* Wc_coff     = (const float*)d_in[10];
    float* out = (float*)d_out;
    int E = in_sizes[2] / 2;

    k_edges<<<(E + 1023) / 1024, 256>>>(edge, E, Ws_w, Ws_b, as_w, Ws_coff, Wc_coff);
    k_gemm<<<Nn / BM, 256>>>(h_context, Wc_w, Wc_b, ac_w, h_structure);
    k_attn<<<Nn, 256>>>(out, Ws_coff, Wc_coff);
}